// round 4
// baseline (speedup 1.0000x reference)
#include <cuda_runtime.h>
#include <math.h>
#include <stdint.h>

#define BB 2
#define SS 2048
#define HH 1024
#define NH 16
#define HD 64
#define BH 32
#define NROWS 4096

// scratch (static __device__ arrays; no runtime allocation)
__device__ float g_q[(size_t)BH * SS * HD];
__device__ float g_k[(size_t)BH * SS * HD];
__device__ float g_v[(size_t)BH * SS * HD];
__device__ float g_kt[(size_t)BH * HD * SS];      // K transposed: [bh][d][s]
__device__ float g_wt[3 * (size_t)HH * HH];       // Wq,Wk,Wv transposed: [k][n]

typedef unsigned long long u64;

// ---- packed fp32x2 helpers (sm_103a FFMA2) ----
__device__ __forceinline__ u64 bcast2(float x) {
    u64 d; unsigned int u = __float_as_uint(x);
    asm("mov.b64 %0, {%1,%2};" : "=l"(d) : "r"(u), "r"(u));
    return d;
}
__device__ __forceinline__ u64 ffma2(u64 a, u64 b, u64 c) {
    u64 d;
    asm("fma.rn.f32x2 %0, %1, %2, %3;" : "=l"(d) : "l"(a), "l"(b), "l"(c));
    return d;
}
__device__ __forceinline__ float2 unpk(u64 v) {
    unsigned int lo, hi;
    asm("mov.b64 {%0,%1}, %2;" : "=r"(lo), "=r"(hi) : "l"(v));
    return make_float2(__uint_as_float(lo), __uint_as_float(hi));
}
__device__ __forceinline__ float f4c(const float4& v, int i) {
    return i == 0 ? v.x : i == 1 ? v.y : i == 2 ? v.z : v.w;
}

// ---- cp.async helpers ----
__device__ __forceinline__ void cpa16(void* s, const void* g) {
    unsigned int sa = (unsigned int)__cvta_generic_to_shared(s);
    asm volatile("cp.async.ca.shared.global [%0], [%1], 16;" :: "r"(sa), "l"(g));
}
#define CPA_COMMIT  asm volatile("cp.async.commit_group;")
#define CPA_WAIT1   asm volatile("cp.async.wait_group 1;")
#define CPA_WAIT0   asm volatile("cp.async.wait_group 0;")

// ---------------------------------------------------------------------------
// Transpose all three W matrices: g_wt[z][k][n] = W_z[n][k]
// ---------------------------------------------------------------------------
__global__ __launch_bounds__(256) void transpose_w3(
    const float* __restrict__ Wq, const float* __restrict__ Wk,
    const float* __restrict__ Wv, float* __restrict__ outp)
{
    __shared__ float t[32][33];
    const int z = blockIdx.z;
    const float* in = z == 0 ? Wq : z == 1 ? Wk : Wv;
    float* op = outp + (size_t)z * HH * HH;
    const int x0 = blockIdx.x * 32, y0 = blockIdx.y * 32;
    const int x = threadIdx.x, y = threadIdx.y;   // 32 x 8
    for (int i = y; i < 32; i += 8) t[i][x] = in[(size_t)(y0 + i) * HH + x0 + x];
    __syncthreads();
    for (int i = y; i < 32; i += 8) op[(size_t)(x0 + i) * HH + y0 + x] = t[x][i];
}

// ---------------------------------------------------------------------------
// Transpose K: [bh][s][d] -> [bh][d][s]
// ---------------------------------------------------------------------------
__global__ __launch_bounds__(256) void transpose_k(
    const float* __restrict__ in, float* __restrict__ outp)
{
    __shared__ float t[32][33];
    const int bh = blockIdx.z;
    const int s0 = blockIdx.x * 32;
    const int d0 = blockIdx.y * 32;
    const int x = threadIdx.x, y = threadIdx.y;   // 32 x 8
    const float* ip = in + ((size_t)bh * SS + s0) * HD + d0;
    for (int i = y; i < 32; i += 8) t[i][x] = ip[(size_t)i * HD + x];
    __syncthreads();
    float* op = outp + ((size_t)bh * HD + d0) * SS + s0;
    for (int i = y; i < 32; i += 8) op[(size_t)i * SS + x] = t[x][i];
}

// ---------------------------------------------------------------------------
// Fused QKV projection GEMM (grid.z selects q/k/v): out = X @ W^T + b,
// scattered to [bh][s][d]. Tile 128x128, BK=32, 8x8 FFMA2 micro-tile,
// 2-stage cp.async + register-level double-buffered smem loads.
// ---------------------------------------------------------------------------
#define APAD 36
#define PROJ_STAGE (128 * APAD + 32 * 128)   // 8704 floats per stage
#define PROJ_SMEM (2 * PROJ_STAGE * 4)

__global__ __launch_bounds__(256) void proj_kernel(
    const float* __restrict__ Xq, const float* __restrict__ Xk,
    const float* __restrict__ Xv, const float* __restrict__ Wt3,
    const float* __restrict__ bq, const float* __restrict__ bk,
    const float* __restrict__ bv,
    float* __restrict__ oq, float* __restrict__ ok, float* __restrict__ ov)
{
    extern __shared__ float sm[];
    const int z = blockIdx.z;
    const float* X    = z == 0 ? Xq : z == 1 ? Xk : Xv;
    const float* Wt   = Wt3 + (size_t)z * HH * HH;
    const float* bias = z == 0 ? bq : z == 1 ? bk : bv;
    float* outp       = z == 0 ? oq : z == 1 ? ok : ov;

    const int tid = threadIdx.x;
    const int tx = tid & 15;           // col group (8 cols)
    const int ty = tid >> 4;           // row group (8 rows)
    const int i0 = blockIdx.y * 128;
    const int j0 = blockIdx.x * 128;

    auto prefetch = [&](int k0, int buf) {
        float* As = sm + buf * PROJ_STAGE;
        float* Bs = As + 128 * APAD;
#pragma unroll
        for (int e = 0; e < 4; e++) {
            int f = e * 256 + tid;
            int r = f >> 3, c4 = f & 7;
            cpa16(&As[r * APAD + c4 * 4], X + (size_t)(i0 + r) * HH + k0 + c4 * 4);
        }
#pragma unroll
        for (int e = 0; e < 4; e++) {
            int f = e * 256 + tid;
            int k = f >> 5, c = f & 31;
            cpa16(&Bs[k * 128 + c * 4], Wt + (size_t)(k0 + k) * HH + j0 + c * 4);
        }
        CPA_COMMIT;
    };

    u64 acc[8][4];
#pragma unroll
    for (int i = 0; i < 8; i++)
#pragma unroll
        for (int j = 0; j < 4; j++) acc[i][j] = 0ull;

    prefetch(0, 0);

    for (int it = 0; it < 32; it++) {
        if (it < 31) { prefetch((it + 1) * 32, (it + 1) & 1); CPA_WAIT1; }
        else         { CPA_WAIT0; }
        __syncthreads();
        const float* As = sm + (it & 1) * PROJ_STAGE;
        const float* Bs = As + 128 * APAD;

        float4 aq[2][8];
        ulonglong2 b0[2], b1[2];
#pragma unroll
        for (int i = 0; i < 8; i++)
            aq[0][i] = *(const float4*)&As[(ty * 8 + i) * APAD];
        {
            const float* bp = &Bs[tx * 8];
            b0[0] = *(const ulonglong2*)bp;
            b1[0] = *(const ulonglong2*)(bp + 4);
        }
#pragma unroll
        for (int k4 = 0; k4 < 8; k4++) {
            const int cur = k4 & 1;
            if (k4 < 7) {
#pragma unroll
                for (int i = 0; i < 8; i++)
                    aq[cur ^ 1][i] = *(const float4*)&As[(ty * 8 + i) * APAD + (k4 + 1) * 4];
            }
#pragma unroll
            for (int dd = 0; dd < 4; dd++) {
                const int kidx = k4 * 4 + dd;
                const int bc = kidx & 1;
                if (kidx < 31) {
                    const float* bp = &Bs[(kidx + 1) * 128 + tx * 8];
                    b0[bc ^ 1] = *(const ulonglong2*)bp;
                    b1[bc ^ 1] = *(const ulonglong2*)(bp + 4);
                }
#pragma unroll
                for (int i = 0; i < 8; i++) {
                    u64 ap = bcast2(f4c(aq[cur][i], dd));
                    acc[i][0] = ffma2(ap, b0[bc].x, acc[i][0]);
                    acc[i][1] = ffma2(ap, b0[bc].y, acc[i][1]);
                    acc[i][2] = ffma2(ap, b1[bc].x, acc[i][2]);
                    acc[i][3] = ffma2(ap, b1[bc].y, acc[i][3]);
                }
            }
        }
        __syncthreads();
    }

    const int col = j0 + tx * 8;
    const int h = col >> 6, d = col & 63;
    float4 bb0 = *(const float4*)(bias + col);
    float4 bb1 = *(const float4*)(bias + col + 4);
#pragma unroll
    for (int i = 0; i < 8; i++) {
        int r = i0 + ty * 8 + i;
        int b = r >> 11, s = r & 2047;
        float2 p0 = unpk(acc[i][0]), p1 = unpk(acc[i][1]);
        float2 p2 = unpk(acc[i][2]), p3 = unpk(acc[i][3]);
        float4 o0 = make_float4(p0.x + bb0.x, p0.y + bb0.y, p1.x + bb0.z, p1.y + bb0.w);
        float4 o1 = make_float4(p2.x + bb1.x, p2.y + bb1.y, p3.x + bb1.z, p3.y + bb1.w);
        float* op = outp + (((size_t)(b * NH + h)) * SS + s) * HD + d;
        *(float4*)op = o0;
        *(float4*)(op + 4) = o1;
    }
}

// ---------------------------------------------------------------------------
// Score GEMM: wout[bh][i][j] = 0.25 * sum_d q[i,d]*k[j,d].
// Block = 128 i-rows x (4 consecutive 128-wide j-tiles). Q tile loaded once,
// K^T tiles double-buffered (cp.async); smem loads double-buffered in regs.
// ---------------------------------------------------------------------------
#define QPAD 68
#define KSTAGE (64 * 128)
#define SCORE_SMEM ((128 * QPAD + 2 * KSTAGE) * 4)

__global__ __launch_bounds__(256) void score_kernel(float* __restrict__ wout)
{
    extern __shared__ float sm[];
    float* Qs = sm;                       // [128][QPAD]
    float* Kbuf = sm + 128 * QPAD;        // 2 x [64][128]
    const int tid = threadIdx.x;
    const int tx = tid & 15, ty = tid >> 4;
    const int bh = blockIdx.z;
    const int i0 = blockIdx.y * 128;
    const int jb0 = blockIdx.x * 4;

    const float* Qp = g_q + ((size_t)bh * SS + i0) * HD;
    const float* Ktp = g_kt + (size_t)bh * HD * SS;

#pragma unroll
    for (int e = 0; e < 8; e++) {
        int f = e * 256 + tid;
        int r = f >> 4, c4 = f & 15;
        cpa16(&Qs[r * QPAD + c4 * 4], Qp + (size_t)r * HD + c4 * 4);
    }
    CPA_COMMIT;

    auto prefetchK = [&](int j0, int buf) {
        float* Ks = Kbuf + buf * KSTAGE;
#pragma unroll
        for (int e = 0; e < 8; e++) {
            int f = e * 256 + tid;
            int d = f >> 5, c = f & 31;
            cpa16(&Ks[d * 128 + c * 4], Ktp + (size_t)d * SS + j0 + c * 4);
        }
        CPA_COMMIT;
    };
    prefetchK(jb0 * 128, 0);

    for (int jt = 0; jt < 4; jt++) {
        const int j0 = (jb0 + jt) * 128;
        if (jt < 3) { prefetchK(j0 + 128, (jt + 1) & 1); CPA_WAIT1; }
        else        { CPA_WAIT0; }
        __syncthreads();
        const float* Ks = Kbuf + (jt & 1) * KSTAGE;

        u64 acc[8][4];
#pragma unroll
        for (int i = 0; i < 8; i++)
#pragma unroll
            for (int j = 0; j < 4; j++) acc[i][j] = 0ull;

        float4 aq[2][8];
        ulonglong2 b0[2], b1[2];
#pragma unroll
        for (int i = 0; i < 8; i++)
            aq[0][i] = *(const float4*)&Qs[(ty * 8 + i) * QPAD];
        {
            const float* bp = &Ks[tx * 8];
            b0[0] = *(const ulonglong2*)bp;
            b1[0] = *(const ulonglong2*)(bp + 4);
        }
#pragma unroll
        for (int d4 = 0; d4 < 16; d4++) {
            const int cur = d4 & 1;
            if (d4 < 15) {
#pragma unroll
                for (int i = 0; i < 8; i++)
                    aq[cur ^ 1][i] = *(const float4*)&Qs[(ty * 8 + i) * QPAD + (d4 + 1) * 4];
            }
#pragma unroll
            for (int dd = 0; dd < 4; dd++) {
                const int kidx = d4 * 4 + dd;
                const int bc = kidx & 1;
                if (kidx < 63) {
                    const float* bp = &Ks[(kidx + 1) * 128 + tx * 8];
                    b0[bc ^ 1] = *(const ulonglong2*)bp;
                    b1[bc ^ 1] = *(const ulonglong2*)(bp + 4);
                }
#pragma unroll
                for (int i = 0; i < 8; i++) {
                    u64 ap = bcast2(f4c(aq[cur][i], dd));
                    acc[i][0] = ffma2(ap, b0[bc].x, acc[i][0]);
                    acc[i][1] = ffma2(ap, b0[bc].y, acc[i][1]);
                    acc[i][2] = ffma2(ap, b1[bc].x, acc[i][2]);
                    acc[i][3] = ffma2(ap, b1[bc].y, acc[i][3]);
                }
            }
        }

#pragma unroll
        for (int i = 0; i < 8; i++) {
            float2 p0 = unpk(acc[i][0]), p1 = unpk(acc[i][1]);
            float2 p2 = unpk(acc[i][2]), p3 = unpk(acc[i][3]);
            float4 o0 = make_float4(p0.x * 0.25f, p0.y * 0.25f, p1.x * 0.25f, p1.y * 0.25f);
            float4 o1 = make_float4(p2.x * 0.25f, p2.y * 0.25f, p3.x * 0.25f, p3.y * 0.25f);
            float* op = wout + ((size_t)bh * SS + i0 + ty * 8 + i) * SS + j0 + tx * 8;
            *(float4*)op = o0;
            *(float4*)(op + 4) = o1;
        }
        __syncthreads();
    }
}

// ---------------------------------------------------------------------------
// Row softmax + threshold prune + L1 renorm, in place (exact fp32 path).
// One warp per row; 2048 floats in 64 regs/lane.
// ---------------------------------------------------------------------------
__global__ __launch_bounds__(256) void softmax_kernel(
    const unsigned char* __restrict__ mask, float* __restrict__ w)
{
    const int lane = threadIdx.x & 31;
    const size_t row = (size_t)blockIdx.x * 8 + (threadIdx.x >> 5);
    const int b = (int)(row >> 15);
    float4* rp = (float4*)(w + row * SS);
    const uchar4* mp = (const uchar4*)(mask + (size_t)b * SS);

    float x[64];
    float mx = -3.0e38f;
#pragma unroll
    for (int v = 0; v < 16; v++) {
        float4 t = rp[lane + v * 32];
        uchar4 m = mp[lane + v * 32];
        x[v * 4 + 0] = m.x ? -1e30f : t.x;
        x[v * 4 + 1] = m.y ? -1e30f : t.y;
        x[v * 4 + 2] = m.z ? -1e30f : t.z;
        x[v * 4 + 3] = m.w ? -1e30f : t.w;
    }
#pragma unroll
    for (int i = 0; i < 64; i++) mx = fmaxf(mx, x[i]);
#pragma unroll
    for (int o = 16; o; o >>= 1) mx = fmaxf(mx, __shfl_xor_sync(0xffffffffu, mx, o));

    float z = 0.f;
#pragma unroll
    for (int i = 0; i < 64; i++) {
        float e = __expf(x[i] - mx);
        x[i] = e;
        z += e;
    }
#pragma unroll
    for (int o = 16; o; o >>= 1) z += __shfl_xor_sync(0xffffffffu, z, o);

    const float cut = 0.01f * z;
    float sk = 0.f;
#pragma unroll
    for (int i = 0; i < 64; i++)
        if (x[i] >= cut) sk += x[i];
#pragma unroll
    for (int o = 16; o; o >>= 1) sk += __shfl_xor_sync(0xffffffffu, sk, o);
    const float inv = sk > 0.f ? 1.f / sk : 0.f;

#pragma unroll
    for (int v = 0; v < 16; v++) {
        float4 o4;
        o4.x = x[v * 4 + 0] >= cut ? x[v * 4 + 0] * inv : 0.f;
        o4.y = x[v * 4 + 1] >= cut ? x[v * 4 + 1] * inv : 0.f;
        o4.z = x[v * 4 + 2] >= cut ? x[v * 4 + 2] * inv : 0.f;
        o4.w = x[v * 4 + 3] >= cut ? x[v * 4 + 3] * inv : 0.f;
        rp[lane + v * 32] = o4;
    }
}

// ---------------------------------------------------------------------------
// PV GEMM: out[b][s][h*64+d] = sum_j W[bh][i][j] * V[bh][j][d].
// Tile 256 rows x 64 cols, k-chunk 64, 8x8 micro (tx: 8 col-groups of 8),
// 2-stage cp.async + register double-buffered smem loads.
// ---------------------------------------------------------------------------
#define WPAD 68
#define PV_STAGE (256 * WPAD + 64 * 64)     // 21504 floats per stage
#define PV_SMEM (2 * PV_STAGE * 4)

__global__ __launch_bounds__(256) void pv_kernel(
    const float* __restrict__ wts, float* __restrict__ outp)
{
    extern __shared__ float psm[];
    const int tid = threadIdx.x;
    const int tx = tid & 7;            // col group (8 cols of 64)
    const int ty = tid >> 3;           // row group (0..31, 8 rows each)
    const int bh = blockIdx.y;
    const int b = bh >> 4, h = bh & 15;
    const int i0 = blockIdx.x * 256;
    const float* Wp = wts + ((size_t)bh * SS + i0) * SS;
    const float* Vp = g_v + (size_t)bh * SS * HD;

    auto prefetch = [&](int kc, int buf) {
        float* Wt = psm + buf * PV_STAGE;
        float* Vt = Wt + 256 * WPAD;
#pragma unroll
        for (int e = 0; e < 16; e++) {
            int f = e * 256 + tid;
            int r = f >> 4, c4 = f & 15;
            cpa16(&Wt[r * WPAD + c4 * 4], Wp + (size_t)r * SS + kc + c4 * 4);
        }
#pragma unroll
        for (int e = 0; e < 4; e++) {
            int f = e * 256 + tid;
            int j = f >> 4, c4 = f & 15;
            cpa16(&Vt[j * 64 + c4 * 4], Vp + (size_t)(kc + j) * HD + c4 * 4);
        }
        CPA_COMMIT;
    };

    u64 acc[8][4];
#pragma unroll
    for (int i = 0; i < 8; i++)
#pragma unroll
        for (int j = 0; j < 4; j++) acc[i][j] = 0ull;

    prefetch(0, 0);

    for (int it = 0; it < 32; it++) {
        if (it < 31) { prefetch((it + 1) * 64, (it + 1) & 1); CPA_WAIT1; }
        else         { CPA_WAIT0; }
        __syncthreads();
        const float* Wt = psm + (it & 1) * PV_STAGE;
        const float* Vt = Wt + 256 * WPAD;

        float4 aw[2][8];
        ulonglong2 b0[2], b1[2];
#pragma unroll
        for (int i = 0; i < 8; i++)
            aw[0][i] = *(const float4*)&Wt[(ty * 8 + i) * WPAD];
        {
            const float* bp = &Vt[tx * 8];
            b0[0] = *(const ulonglong2*)bp;
            b1[0] = *(const ulonglong2*)(bp + 4);
        }
#pragma unroll
        for (int k4 = 0; k4 < 16; k4++) {
            const int cur = k4 & 1;
            if (k4 < 15) {
#pragma unroll
                for (int i = 0; i < 8; i++)
                    aw[cur ^ 1][i] = *(const float4*)&Wt[(ty * 8 + i) * WPAD + (k4 + 1) * 4];
            }
#pragma unroll
            for (int dd = 0; dd < 4; dd++) {
                const int kidx = k4 * 4 + dd;
                const int bc = kidx & 1;
                if (kidx < 63) {
                    const float* bp = &Vt[(kidx + 1) * 64 + tx * 8];
                    b0[bc ^ 1] = *(const ulonglong2*)bp;
                    b1[bc ^ 1] = *(const ulonglong2*)(bp + 4);
                }
#pragma unroll
                for (int i = 0; i < 8; i++) {
                    u64 ap = bcast2(f4c(aw[cur][i], dd));
                    acc[i][0] = ffma2(ap, b0[bc].x, acc[i][0]);
                    acc[i][1] = ffma2(ap, b0[bc].y, acc[i][1]);
                    acc[i][2] = ffma2(ap, b1[bc].x, acc[i][2]);
                    acc[i][3] = ffma2(ap, b1[bc].y, acc[i][3]);
                }
            }
        }
        __syncthreads();
    }

#pragma unroll
    for (int i = 0; i < 8; i++) {
        float2 p0 = unpk(acc[i][0]), p1 = unpk(acc[i][1]);
        float2 p2 = unpk(acc[i][2]), p3 = unpk(acc[i][3]);
        float4 o0 = make_float4(p0.x, p0.y, p1.x, p1.y);
        float4 o1 = make_float4(p2.x, p2.y, p3.x, p3.y);
        int s = i0 + ty * 8 + i;
        float* op = outp + ((size_t)b * SS + s) * HH + h * HD + tx * 8;
        *(float4*)op = o0;
        *(float4*)(op + 4) = o1;
    }
}

// ---------------------------------------------------------------------------
extern "C" void kernel_launch(void* const* d_in, const int* in_sizes, int n_in,
                              void* d_out, int out_size)
{
    const float* query = (const float*)d_in[0];
    const float* key   = (const float*)d_in[1];
    const float* value = (const float*)d_in[2];
    const unsigned char* mask = (const unsigned char*)d_in[3];
    const float* Wq = (const float*)d_in[4];
    const float* bq = (const float*)d_in[5];
    const float* Wk = (const float*)d_in[6];
    const float* bk = (const float*)d_in[7];
    const float* Wv = (const float*)d_in[8];
    const float* bv = (const float*)d_in[9];

    float* outp = (float*)d_out;                        // [B,S,H]
    float* wts  = outp + (size_t)BB * SS * HH;          // [B,h,S,S]

    float *gq, *gk, *gv, *gkt, *gwt;
    cudaGetSymbolAddress((void**)&gq, g_q);
    cudaGetSymbolAddress((void**)&gk, g_k);
    cudaGetSymbolAddress((void**)&gv, g_v);
    cudaGetSymbolAddress((void**)&gkt, g_kt);
    cudaGetSymbolAddress((void**)&gwt, g_wt);

    cudaFuncSetAttribute(proj_kernel, cudaFuncAttributeMaxDynamicSharedMemorySize,
                         PROJ_SMEM);
    cudaFuncSetAttribute(score_kernel, cudaFuncAttributeMaxDynamicSharedMemorySize,
                         SCORE_SMEM);
    cudaFuncSetAttribute(pv_kernel, cudaFuncAttributeMaxDynamicSharedMemorySize,
                         PV_SMEM);

    dim3 tb(32, 8);

    transpose_w3<<<dim3(32, 32, 3), tb>>>(Wq, Wk, Wv, gwt);

    dim3 pgrid(HH / 128, NROWS / 128, 3);
    proj_kernel<<<pgrid, 256, PROJ_SMEM>>>(query, key, value, gwt, bq, bk, bv, gq, gk, gv);

    dim3 tkgrid(SS / 32, HD / 32, BH);
    transpose_k<<<tkgrid, tb>>>(gk, gkt);

    dim3 sgrid(SS / 128 / 4, SS / 128, BH);
    score_kernel<<<sgrid, 256, SCORE_SMEM>>>(wts);

    softmax_kernel<<<(BH * SS) / 8, 256>>>(mask, wts);

    dim3 vgrid(SS / 256, BH);
    pv_kernel<<<vgrid, 256, PV_SMEM>>>(wts, outp);
}

// round 5
// speedup vs baseline: 1.0795x; 1.0795x over previous
#include <cuda_runtime.h>
#include <math.h>
#include <stdint.h>

#define BB 2
#define SS 2048
#define HH 1024
#define NH 16
#define HD 64
#define BH 32
#define NROWS 4096

// scratch (static __device__ arrays; no runtime allocation)
__device__ float g_q[(size_t)BH * SS * HD];
__device__ float g_k[(size_t)BH * SS * HD];
__device__ float g_v[(size_t)BH * SS * HD];
__device__ float g_kt[(size_t)BH * HD * SS];      // K transposed: [bh][d][s]
__device__ float g_wt[3 * (size_t)HH * HH];       // Wq,Wk,Wv transposed: [k][n]

typedef unsigned long long u64;

// ---- packed fp32x2 helpers (sm_103a FFMA2) ----
__device__ __forceinline__ u64 bcast2(float x) {
    u64 d; unsigned int u = __float_as_uint(x);
    asm("mov.b64 %0, {%1,%2};" : "=l"(d) : "r"(u), "r"(u));
    return d;
}
__device__ __forceinline__ u64 ffma2(u64 a, u64 b, u64 c) {
    u64 d;
    asm("fma.rn.f32x2 %0, %1, %2, %3;" : "=l"(d) : "l"(a), "l"(b), "l"(c));
    return d;
}
__device__ __forceinline__ float2 unpk(u64 v) {
    unsigned int lo, hi;
    asm("mov.b64 {%0,%1}, %2;" : "=r"(lo), "=r"(hi) : "l"(v));
    return make_float2(__uint_as_float(lo), __uint_as_float(hi));
}
__device__ __forceinline__ float f4c(const float4& v, int i) {
    return i == 0 ? v.x : i == 1 ? v.y : i == 2 ? v.z : v.w;
}

// ---- cp.async helpers ----
__device__ __forceinline__ void cpa16(void* s, const void* g) {
    unsigned int sa = (unsigned int)__cvta_generic_to_shared(s);
    asm volatile("cp.async.ca.shared.global [%0], [%1], 16;" :: "r"(sa), "l"(g));
}
#define CPA_COMMIT  asm volatile("cp.async.commit_group;")
#define CPA_WAIT1   asm volatile("cp.async.wait_group 1;")
#define CPA_WAIT0   asm volatile("cp.async.wait_group 0;")

// ---------------------------------------------------------------------------
// Transpose all three W matrices: g_wt[z][k][n] = W_z[n][k]
// ---------------------------------------------------------------------------
__global__ __launch_bounds__(256) void transpose_w3(
    const float* __restrict__ Wq, const float* __restrict__ Wk,
    const float* __restrict__ Wv, float* __restrict__ outp)
{
    __shared__ float t[32][33];
    const int z = blockIdx.z;
    const float* in = z == 0 ? Wq : z == 1 ? Wk : Wv;
    float* op = outp + (size_t)z * HH * HH;
    const int x0 = blockIdx.x * 32, y0 = blockIdx.y * 32;
    const int x = threadIdx.x, y = threadIdx.y;   // 32 x 8
    for (int i = y; i < 32; i += 8) t[i][x] = in[(size_t)(y0 + i) * HH + x0 + x];
    __syncthreads();
    for (int i = y; i < 32; i += 8) op[(size_t)(x0 + i) * HH + y0 + x] = t[x][i];
}

// ---------------------------------------------------------------------------
// Transpose K: [bh][s][d] -> [bh][d][s]
// ---------------------------------------------------------------------------
__global__ __launch_bounds__(256) void transpose_k(
    const float* __restrict__ in, float* __restrict__ outp)
{
    __shared__ float t[32][33];
    const int bh = blockIdx.z;
    const int s0 = blockIdx.x * 32;
    const int d0 = blockIdx.y * 32;
    const int x = threadIdx.x, y = threadIdx.y;   // 32 x 8
    const float* ip = in + ((size_t)bh * SS + s0) * HD + d0;
    for (int i = y; i < 32; i += 8) t[i][x] = ip[(size_t)i * HD + x];
    __syncthreads();
    float* op = outp + ((size_t)bh * HD + d0) * SS + s0;
    for (int i = y; i < 32; i += 8) op[(size_t)i * SS + x] = t[x][i];
}

// ---------------------------------------------------------------------------
// Fused QKV projection GEMM (grid.z selects q/k/v): out = X @ W^T + b,
// scattered to [bh][s][d]. Tile 128x128, BK=32, 8x8 FFMA2 micro-tile,
// 2-stage cp.async, 2 CTAs/SM (128-reg cap).
// ---------------------------------------------------------------------------
#define APAD 36
#define PROJ_STAGE (128 * APAD + 32 * 128)   // 8704 floats per stage
#define PROJ_SMEM (2 * PROJ_STAGE * 4)

__global__ __launch_bounds__(256, 2) void proj_kernel(
    const float* __restrict__ Xq, const float* __restrict__ Xk,
    const float* __restrict__ Xv, const float* __restrict__ Wt3,
    const float* __restrict__ bq, const float* __restrict__ bk,
    const float* __restrict__ bv,
    float* __restrict__ oq, float* __restrict__ ok, float* __restrict__ ov)
{
    extern __shared__ float sm[];
    const int z = blockIdx.z;
    const float* X    = z == 0 ? Xq : z == 1 ? Xk : Xv;
    const float* Wt   = Wt3 + (size_t)z * HH * HH;
    const float* bias = z == 0 ? bq : z == 1 ? bk : bv;
    float* outp       = z == 0 ? oq : z == 1 ? ok : ov;

    const int tid = threadIdx.x;
    const int tx = tid & 15;           // col group (8 cols)
    const int ty = tid >> 4;           // row group (8 rows)
    const int i0 = blockIdx.y * 128;
    const int j0 = blockIdx.x * 128;

    auto prefetch = [&](int k0, int buf) {
        float* As = sm + buf * PROJ_STAGE;
        float* Bs = As + 128 * APAD;
#pragma unroll
        for (int e = 0; e < 4; e++) {
            int f = e * 256 + tid;
            int r = f >> 3, c4 = f & 7;
            cpa16(&As[r * APAD + c4 * 4], X + (size_t)(i0 + r) * HH + k0 + c4 * 4);
        }
#pragma unroll
        for (int e = 0; e < 4; e++) {
            int f = e * 256 + tid;
            int k = f >> 5, c = f & 31;
            cpa16(&Bs[k * 128 + c * 4], Wt + (size_t)(k0 + k) * HH + j0 + c * 4);
        }
        CPA_COMMIT;
    };

    u64 acc[8][4];
#pragma unroll
    for (int i = 0; i < 8; i++)
#pragma unroll
        for (int j = 0; j < 4; j++) acc[i][j] = 0ull;

    prefetch(0, 0);

    for (int it = 0; it < 32; it++) {
        if (it < 31) { prefetch((it + 1) * 32, (it + 1) & 1); CPA_WAIT1; }
        else         { CPA_WAIT0; }
        __syncthreads();
        const float* As = sm + (it & 1) * PROJ_STAGE;
        const float* Bs = As + 128 * APAD;
#pragma unroll
        for (int k4 = 0; k4 < 8; k4++) {
            float4 aq[8];
#pragma unroll
            for (int i = 0; i < 8; i++)
                aq[i] = *(const float4*)&As[(ty * 8 + i) * APAD + k4 * 4];
#pragma unroll
            for (int dd = 0; dd < 4; dd++) {
                const float* bp = &Bs[(k4 * 4 + dd) * 128 + tx * 8];
                ulonglong2 b0 = *(const ulonglong2*)bp;
                ulonglong2 b1 = *(const ulonglong2*)(bp + 4);
#pragma unroll
                for (int i = 0; i < 8; i++) {
                    u64 ap = bcast2(f4c(aq[i], dd));
                    acc[i][0] = ffma2(ap, b0.x, acc[i][0]);
                    acc[i][1] = ffma2(ap, b0.y, acc[i][1]);
                    acc[i][2] = ffma2(ap, b1.x, acc[i][2]);
                    acc[i][3] = ffma2(ap, b1.y, acc[i][3]);
                }
            }
        }
        __syncthreads();
    }

    const int col = j0 + tx * 8;
    const int h = col >> 6, d = col & 63;
    float4 bb0 = *(const float4*)(bias + col);
    float4 bb1 = *(const float4*)(bias + col + 4);
#pragma unroll
    for (int i = 0; i < 8; i++) {
        int r = i0 + ty * 8 + i;
        int b = r >> 11, s = r & 2047;
        float2 p0 = unpk(acc[i][0]), p1 = unpk(acc[i][1]);
        float2 p2 = unpk(acc[i][2]), p3 = unpk(acc[i][3]);
        float4 o0 = make_float4(p0.x + bb0.x, p0.y + bb0.y, p1.x + bb0.z, p1.y + bb0.w);
        float4 o1 = make_float4(p2.x + bb1.x, p2.y + bb1.y, p3.x + bb1.z, p3.y + bb1.w);
        float* op = outp + (((size_t)(b * NH + h)) * SS + s) * HD + d;
        *(float4*)op = o0;
        *(float4*)(op + 4) = o1;
    }
}

// ---------------------------------------------------------------------------
// Score GEMM: wout[bh][i][j] = 0.25 * sum_d q[i,d]*k[j,d].
// Block = 128 i-rows x (4 consecutive 128-wide j-tiles). Q tile loaded once,
// K^T tiles double-buffered (cp.async). 2 CTAs/SM (128-reg cap).
// ---------------------------------------------------------------------------
#define QPAD 68
#define KSTAGE (64 * 128)
#define SCORE_SMEM ((128 * QPAD + 2 * KSTAGE) * 4)

__global__ __launch_bounds__(256, 2) void score_kernel(float* __restrict__ wout)
{
    extern __shared__ float sm[];
    float* Qs = sm;                       // [128][QPAD]
    float* Kbuf = sm + 128 * QPAD;        // 2 x [64][128]
    const int tid = threadIdx.x;
    const int tx = tid & 15, ty = tid >> 4;
    const int bh = blockIdx.z;
    const int i0 = blockIdx.y * 128;
    const int jb0 = blockIdx.x * 4;

    const float* Qp = g_q + ((size_t)bh * SS + i0) * HD;
    const float* Ktp = g_kt + (size_t)bh * HD * SS;

#pragma unroll
    for (int e = 0; e < 8; e++) {
        int f = e * 256 + tid;
        int r = f >> 4, c4 = f & 15;
        cpa16(&Qs[r * QPAD + c4 * 4], Qp + (size_t)r * HD + c4 * 4);
    }
    CPA_COMMIT;

    auto prefetchK = [&](int j0, int buf) {
        float* Ks = Kbuf + buf * KSTAGE;
#pragma unroll
        for (int e = 0; e < 8; e++) {
            int f = e * 256 + tid;
            int d = f >> 5, c = f & 31;
            cpa16(&Ks[d * 128 + c * 4], Ktp + (size_t)d * SS + j0 + c * 4);
        }
        CPA_COMMIT;
    };
    prefetchK(jb0 * 128, 0);

    for (int jt = 0; jt < 4; jt++) {
        const int j0 = (jb0 + jt) * 128;
        if (jt < 3) { prefetchK(j0 + 128, (jt + 1) & 1); CPA_WAIT1; }
        else        { CPA_WAIT0; }
        __syncthreads();
        const float* Ks = Kbuf + (jt & 1) * KSTAGE;

        u64 acc[8][4];
#pragma unroll
        for (int i = 0; i < 8; i++)
#pragma unroll
            for (int j = 0; j < 4; j++) acc[i][j] = 0ull;

#pragma unroll 4
        for (int d4 = 0; d4 < 16; d4++) {
            float4 aq[8];
#pragma unroll
            for (int i = 0; i < 8; i++)
                aq[i] = *(const float4*)&Qs[(ty * 8 + i) * QPAD + d4 * 4];
#pragma unroll
            for (int dd = 0; dd < 4; dd++) {
                const float* bp = &Ks[(d4 * 4 + dd) * 128 + tx * 8];
                ulonglong2 b0 = *(const ulonglong2*)bp;
                ulonglong2 b1 = *(const ulonglong2*)(bp + 4);
#pragma unroll
                for (int i = 0; i < 8; i++) {
                    u64 ap = bcast2(f4c(aq[i], dd));
                    acc[i][0] = ffma2(ap, b0.x, acc[i][0]);
                    acc[i][1] = ffma2(ap, b0.y, acc[i][1]);
                    acc[i][2] = ffma2(ap, b1.x, acc[i][2]);
                    acc[i][3] = ffma2(ap, b1.y, acc[i][3]);
                }
            }
        }

#pragma unroll
        for (int i = 0; i < 8; i++) {
            float2 p0 = unpk(acc[i][0]), p1 = unpk(acc[i][1]);
            float2 p2 = unpk(acc[i][2]), p3 = unpk(acc[i][3]);
            float4 o0 = make_float4(p0.x * 0.25f, p0.y * 0.25f, p1.x * 0.25f, p1.y * 0.25f);
            float4 o1 = make_float4(p2.x * 0.25f, p2.y * 0.25f, p3.x * 0.25f, p3.y * 0.25f);
            float* op = wout + ((size_t)bh * SS + i0 + ty * 8 + i) * SS + j0 + tx * 8;
            *(float4*)op = o0;
            *(float4*)(op + 4) = o1;
        }
        __syncthreads();
    }
}

// ---------------------------------------------------------------------------
// Row softmax + threshold prune + L1 renorm, in place (exact fp32 path).
// One warp per row; 2048 floats in 64 regs/lane.
// ---------------------------------------------------------------------------
__global__ __launch_bounds__(256) void softmax_kernel(
    const unsigned char* __restrict__ mask, float* __restrict__ w)
{
    const int lane = threadIdx.x & 31;
    const size_t row = (size_t)blockIdx.x * 8 + (threadIdx.x >> 5);
    const int b = (int)(row >> 15);
    float4* rp = (float4*)(w + row * SS);
    const uchar4* mp = (const uchar4*)(mask + (size_t)b * SS);

    float x[64];
    float mx = -3.0e38f;
#pragma unroll
    for (int v = 0; v < 16; v++) {
        float4 t = rp[lane + v * 32];
        uchar4 m = mp[lane + v * 32];
        x[v * 4 + 0] = m.x ? -1e30f : t.x;
        x[v * 4 + 1] = m.y ? -1e30f : t.y;
        x[v * 4 + 2] = m.z ? -1e30f : t.z;
        x[v * 4 + 3] = m.w ? -1e30f : t.w;
    }
#pragma unroll
    for (int i = 0; i < 64; i++) mx = fmaxf(mx, x[i]);
#pragma unroll
    for (int o = 16; o; o >>= 1) mx = fmaxf(mx, __shfl_xor_sync(0xffffffffu, mx, o));

    float z = 0.f;
#pragma unroll
    for (int i = 0; i < 64; i++) {
        float e = __expf(x[i] - mx);
        x[i] = e;
        z += e;
    }
#pragma unroll
    for (int o = 16; o; o >>= 1) z += __shfl_xor_sync(0xffffffffu, z, o);

    const float cut = 0.01f * z;
    float sk = 0.f;
#pragma unroll
    for (int i = 0; i < 64; i++)
        if (x[i] >= cut) sk += x[i];
#pragma unroll
    for (int o = 16; o; o >>= 1) sk += __shfl_xor_sync(0xffffffffu, sk, o);
    const float inv = sk > 0.f ? 1.f / sk : 0.f;

#pragma unroll
    for (int v = 0; v < 16; v++) {
        float4 o4;
        o4.x = x[v * 4 + 0] >= cut ? x[v * 4 + 0] * inv : 0.f;
        o4.y = x[v * 4 + 1] >= cut ? x[v * 4 + 1] * inv : 0.f;
        o4.z = x[v * 4 + 2] >= cut ? x[v * 4 + 2] * inv : 0.f;
        o4.w = x[v * 4 + 3] >= cut ? x[v * 4 + 3] * inv : 0.f;
        rp[lane + v * 32] = o4;
    }
}

// ---------------------------------------------------------------------------
// PV GEMM: out[b][s][h*64+d] = sum_j W[bh][i][j] * V[bh][j][d].
// Tile 128 rows x 64 cols, k-chunk 64, 8x4 FFMA2 micro-tile,
// 2-stage cp.async, 2 CTAs/SM.
// ---------------------------------------------------------------------------
#define WPAD 68
#define PV_STAGE (128 * WPAD + 64 * 64)     // 12800 floats per stage
#define PV_SMEM (2 * PV_STAGE * 4)

__global__ __launch_bounds__(256, 2) void pv_kernel(
    const float* __restrict__ wts, float* __restrict__ outp)
{
    extern __shared__ float psm[];
    const int tid = threadIdx.x;
    const int tx = tid & 15;           // col group (4 cols of 64)
    const int ty = tid >> 4;           // row group (8 rows)
    const int bh = blockIdx.y;
    const int b = bh >> 4, h = bh & 15;
    const int i0 = blockIdx.x * 128;
    const float* Wp = wts + ((size_t)bh * SS + i0) * SS;
    const float* Vp = g_v + (size_t)bh * SS * HD;

    auto prefetch = [&](int kc, int buf) {
        float* Wt = psm + buf * PV_STAGE;
        float* Vt = Wt + 128 * WPAD;
#pragma unroll
        for (int e = 0; e < 8; e++) {
            int f = e * 256 + tid;
            int r = f >> 4, c4 = f & 15;
            cpa16(&Wt[r * WPAD + c4 * 4], Wp + (size_t)r * SS + kc + c4 * 4);
        }
#pragma unroll
        for (int e = 0; e < 4; e++) {
            int f = e * 256 + tid;
            int j = f >> 4, c4 = f & 15;
            cpa16(&Vt[j * 64 + c4 * 4], Vp + (size_t)(kc + j) * HD + c4 * 4);
        }
        CPA_COMMIT;
    };

    u64 acc[8][2];
#pragma unroll
    for (int i = 0; i < 8; i++) { acc[i][0] = 0ull; acc[i][1] = 0ull; }

    prefetch(0, 0);

    for (int it = 0; it < 32; it++) {
        if (it < 31) { prefetch((it + 1) * 64, (it + 1) & 1); CPA_WAIT1; }
        else         { CPA_WAIT0; }
        __syncthreads();
        const float* Wt = psm + (it & 1) * PV_STAGE;
        const float* Vt = Wt + 128 * WPAD;
#pragma unroll
        for (int k4 = 0; k4 < 16; k4++) {
            float4 aw[8];
#pragma unroll
            for (int i = 0; i < 8; i++)
                aw[i] = *(const float4*)&Wt[(ty * 8 + i) * WPAD + k4 * 4];
#pragma unroll
            for (int dd = 0; dd < 4; dd++) {
                ulonglong2 bv = *(const ulonglong2*)&Vt[(k4 * 4 + dd) * 64 + tx * 4];
#pragma unroll
                for (int i = 0; i < 8; i++) {
                    u64 ap = bcast2(f4c(aw[i], dd));
                    acc[i][0] = ffma2(ap, bv.x, acc[i][0]);
                    acc[i][1] = ffma2(ap, bv.y, acc[i][1]);
                }
            }
        }
        __syncthreads();
    }

#pragma unroll
    for (int i = 0; i < 8; i++) {
        float2 p0 = unpk(acc[i][0]), p1 = unpk(acc[i][1]);
        float4 o4 = make_float4(p0.x, p0.y, p1.x, p1.y);
        int s = i0 + ty * 8 + i;
        *(float4*)(outp + ((size_t)b * SS + s) * HH + h * HD + tx * 4) = o4;
    }
}

// ---------------------------------------------------------------------------
extern "C" void kernel_launch(void* const* d_in, const int* in_sizes, int n_in,
                              void* d_out, int out_size)
{
    const float* query = (const float*)d_in[0];
    const float* key   = (const float*)d_in[1];
    const float* value = (const float*)d_in[2];
    const unsigned char* mask = (const unsigned char*)d_in[3];
    const float* Wq = (const float*)d_in[4];
    const float* bq = (const float*)d_in[5];
    const float* Wk = (const float*)d_in[6];
    const float* bk = (const float*)d_in[7];
    const float* Wv = (const float*)d_in[8];
    const float* bv = (const float*)d_in[9];

    float* outp = (float*)d_out;                        // [B,S,H]
    float* wts  = outp + (size_t)BB * SS * HH;          // [B,h,S,S]

    float *gq, *gk, *gv, *gkt, *gwt;
    cudaGetSymbolAddress((void**)&gq, g_q);
    cudaGetSymbolAddress((void**)&gk, g_k);
    cudaGetSymbolAddress((void**)&gv, g_v);
    cudaGetSymbolAddress((void**)&gkt, g_kt);
    cudaGetSymbolAddress((void**)&gwt, g_wt);

    cudaFuncSetAttribute(proj_kernel, cudaFuncAttributeMaxDynamicSharedMemorySize,
                         PROJ_SMEM);
    cudaFuncSetAttribute(score_kernel, cudaFuncAttributeMaxDynamicSharedMemorySize,
                         SCORE_SMEM);
    cudaFuncSetAttribute(pv_kernel, cudaFuncAttributeMaxDynamicSharedMemorySize,
                         PV_SMEM);

    dim3 tb(32, 8);

    transpose_w3<<<dim3(32, 32, 3), tb>>>(Wq, Wk, Wv, gwt);

    dim3 pgrid(HH / 128, NROWS / 128, 3);
    proj_kernel<<<pgrid, 256, PROJ_SMEM>>>(query, key, value, gwt, bq, bk, bv, gq, gk, gv);

    dim3 tkgrid(SS / 32, HD / 32, BH);
    transpose_k<<<tkgrid, tb>>>(gk, gkt);

    dim3 sgrid(SS / 128 / 4, SS / 128, BH);
    score_kernel<<<sgrid, 256, SCORE_SMEM>>>(wts);

    softmax_kernel<<<(BH * SS) / 8, 256>>>(mask, wts);

    dim3 vgrid(SS / 128, BH);
    pv_kernel<<<vgrid, 256, PV_SMEM>>>(wts, outp);
}

// round 7
// speedup vs baseline: 1.0837x; 1.0039x over previous
#include <cuda_runtime.h>
#include <math.h>
#include <stdint.h>

#define BB 2
#define SS 2048
#define HH 1024
#define NH 16
#define HD 64
#define BH 32
#define NROWS 4096

// scratch (static __device__ arrays; no runtime allocation)
__device__ float g_q[(size_t)BH * SS * HD];
__device__ float g_k[(size_t)BH * SS * HD];
__device__ float g_v[(size_t)BH * SS * HD];
__device__ float g_kt[(size_t)BH * HD * SS];      // K transposed: [bh][d][s]
__device__ float g_wt[3 * (size_t)HH * HH];       // Wq,Wk,Wv transposed: [k][n]

typedef unsigned long long u64;

// ---- packed fp32x2 helpers (sm_103a FFMA2) ----
__device__ __forceinline__ u64 bcast2(float x) {
    u64 d; unsigned int u = __float_as_uint(x);
    asm("mov.b64 %0, {%1,%2};" : "=l"(d) : "r"(u), "r"(u));
    return d;
}
__device__ __forceinline__ u64 ffma2(u64 a, u64 b, u64 c) {
    u64 d;
    asm("fma.rn.f32x2 %0, %1, %2, %3;" : "=l"(d) : "l"(a), "l"(b), "l"(c));
    return d;
}
__device__ __forceinline__ float2 unpk(u64 v) {
    unsigned int lo, hi;
    asm("mov.b64 {%0,%1}, %2;" : "=r"(lo), "=r"(hi) : "l"(v));
    return make_float2(__uint_as_float(lo), __uint_as_float(hi));
}
__device__ __forceinline__ float f4c(const float4& v, int i) {
    return i == 0 ? v.x : i == 1 ? v.y : i == 2 ? v.z : v.w;
}

// ---- cp.async helpers ----
__device__ __forceinline__ void cpa16(void* s, const void* g) {
    unsigned int sa = (unsigned int)__cvta_generic_to_shared(s);
    asm volatile("cp.async.ca.shared.global [%0], [%1], 16;" :: "r"(sa), "l"(g));
}
#define CPA_COMMIT  asm volatile("cp.async.commit_group;")
#define CPA_WAIT1   asm volatile("cp.async.wait_group 1;")
#define CPA_WAIT0   asm volatile("cp.async.wait_group 0;")

// ---------------------------------------------------------------------------
// Transpose all three W matrices: g_wt[z][k][n] = W_z[n][k]
// ---------------------------------------------------------------------------
__global__ __launch_bounds__(256) void transpose_w3(
    const float* __restrict__ Wq, const float* __restrict__ Wk,
    const float* __restrict__ Wv, float* __restrict__ outp)
{
    __shared__ float t[32][33];
    const int z = blockIdx.z;
    const float* in = z == 0 ? Wq : z == 1 ? Wk : Wv;
    float* op = outp + (size_t)z * HH * HH;
    const int x0 = blockIdx.x * 32, y0 = blockIdx.y * 32;
    const int x = threadIdx.x, y = threadIdx.y;   // 32 x 8
    for (int i = y; i < 32; i += 8) t[i][x] = in[(size_t)(y0 + i) * HH + x0 + x];
    __syncthreads();
    for (int i = y; i < 32; i += 8) op[(size_t)(x0 + i) * HH + y0 + x] = t[x][i];
}

// ---------------------------------------------------------------------------
// Transpose K: [bh][s][d] -> [bh][d][s]
// ---------------------------------------------------------------------------
__global__ __launch_bounds__(256) void transpose_k(
    const float* __restrict__ in, float* __restrict__ outp)
{
    __shared__ float t[32][33];
    const int bh = blockIdx.z;
    const int s0 = blockIdx.x * 32;
    const int d0 = blockIdx.y * 32;
    const int x = threadIdx.x, y = threadIdx.y;   // 32 x 8
    const float* ip = in + ((size_t)bh * SS + s0) * HD + d0;
    for (int i = y; i < 32; i += 8) t[i][x] = ip[(size_t)i * HD + x];
    __syncthreads();
    float* op = outp + ((size_t)bh * HD + d0) * SS + s0;
    for (int i = y; i < 32; i += 8) op[(size_t)i * SS + x] = t[x][i];
}

// ---------------------------------------------------------------------------
// Fused QKV projection GEMM (grid.z selects q/k/v): out = X @ W^T + b,
// scattered to [bh][s][d]. Tile 64(M)x128(N), BK=32, 8x8 FFMA2 micro-tile,
// 128 threads, 4 CTAs/SM, 2-stage cp.async.
// ---------------------------------------------------------------------------
#define APAD 36
#define PROJ_STAGE (64 * APAD + 32 * 128)    // 6400 floats per stage
#define PROJ_SMEM (2 * PROJ_STAGE * 4)       // 51.2 KB

__global__ __launch_bounds__(128, 4) void proj_kernel(
    const float* __restrict__ Xq, const float* __restrict__ Xk,
    const float* __restrict__ Xv, const float* __restrict__ Wt3,
    const float* __restrict__ bq, const float* __restrict__ bk,
    const float* __restrict__ bv,
    float* __restrict__ oq, float* __restrict__ ok, float* __restrict__ ov)
{
    extern __shared__ float sm[];
    const int z = blockIdx.z;
    const float* X    = z == 0 ? Xq : z == 1 ? Xk : Xv;
    const float* Wt   = Wt3 + (size_t)z * HH * HH;
    const float* bias = z == 0 ? bq : z == 1 ? bk : bv;
    float* outp       = z == 0 ? oq : z == 1 ? ok : ov;

    const int tid = threadIdx.x;
    const int tx = tid & 15;           // col group (8 cols)
    const int ty = tid >> 4;           // row group (8 rows), 0..7
    const int i0 = blockIdx.y * 64;
    const int j0 = blockIdx.x * 128;

    auto prefetch = [&](int k0, int buf) {
        float* As = sm + buf * PROJ_STAGE;
        float* Bs = As + 64 * APAD;
        // A: 64 rows x 32 k = 2048 floats -> 4 cpa16/thread
#pragma unroll
        for (int e = 0; e < 4; e++) {
            int f = e * 128 + tid;
            int r = f >> 3, c4 = f & 7;
            cpa16(&As[r * APAD + c4 * 4], X + (size_t)(i0 + r) * HH + k0 + c4 * 4);
        }
        // B: 32 k x 128 n = 4096 floats -> 8 cpa16/thread
#pragma unroll
        for (int e = 0; e < 8; e++) {
            int f = e * 128 + tid;
            int k = f >> 5, c = f & 31;
            cpa16(&Bs[k * 128 + c * 4], Wt + (size_t)(k0 + k) * HH + j0 + c * 4);
        }
        CPA_COMMIT;
    };

    u64 acc[8][4];
#pragma unroll
    for (int i = 0; i < 8; i++)
#pragma unroll
        for (int j = 0; j < 4; j++) acc[i][j] = 0ull;

    prefetch(0, 0);

    for (int it = 0; it < 32; it++) {
        if (it < 31) { prefetch((it + 1) * 32, (it + 1) & 1); CPA_WAIT1; }
        else         { CPA_WAIT0; }
        __syncthreads();
        const float* As = sm + (it & 1) * PROJ_STAGE;
        const float* Bs = As + 64 * APAD;
#pragma unroll
        for (int k4 = 0; k4 < 8; k4++) {
            float4 aq[8];
#pragma unroll
            for (int i = 0; i < 8; i++)
                aq[i] = *(const float4*)&As[(ty * 8 + i) * APAD + k4 * 4];
#pragma unroll
            for (int dd = 0; dd < 4; dd++) {
                const float* bp = &Bs[(k4 * 4 + dd) * 128 + tx * 8];
                ulonglong2 b0 = *(const ulonglong2*)bp;
                ulonglong2 b1 = *(const ulonglong2*)(bp + 4);
#pragma unroll
                for (int i = 0; i < 8; i++) {
                    u64 ap = bcast2(f4c(aq[i], dd));
                    acc[i][0] = ffma2(ap, b0.x, acc[i][0]);
                    acc[i][1] = ffma2(ap, b0.y, acc[i][1]);
                    acc[i][2] = ffma2(ap, b1.x, acc[i][2]);
                    acc[i][3] = ffma2(ap, b1.y, acc[i][3]);
                }
            }
        }
        __syncthreads();
    }

    const int col = j0 + tx * 8;
    const int h = col >> 6, d = col & 63;
    float4 bb0 = *(const float4*)(bias + col);
    float4 bb1 = *(const float4*)(bias + col + 4);
#pragma unroll
    for (int i = 0; i < 8; i++) {
        int r = i0 + ty * 8 + i;
        int b = r >> 11, s = r & 2047;
        float2 p0 = unpk(acc[i][0]), p1 = unpk(acc[i][1]);
        float2 p2 = unpk(acc[i][2]), p3 = unpk(acc[i][3]);
        float4 o0 = make_float4(p0.x + bb0.x, p0.y + bb0.y, p1.x + bb0.z, p1.y + bb0.w);
        float4 o1 = make_float4(p2.x + bb1.x, p2.y + bb1.y, p3.x + bb1.z, p3.y + bb1.w);
        float* op = outp + (((size_t)(b * NH + h)) * SS + s) * HD + d;
        *(float4*)op = o0;
        *(float4*)(op + 4) = o1;
    }
}

// ---------------------------------------------------------------------------
// Score GEMM: wout[bh][i][j] = 0.25 * sum_d q[i,d]*k[j,d].
// Block = 128 i-rows x (4 consecutive 128-wide j-tiles). Q tile loaded once,
// K^T tiles double-buffered (cp.async). 2 CTAs/SM (128-reg cap).
// ---------------------------------------------------------------------------
#define QPAD 68
#define KSTAGE (64 * 128)
#define SCORE_SMEM ((128 * QPAD + 2 * KSTAGE) * 4)

__global__ __launch_bounds__(256, 2) void score_kernel(float* __restrict__ wout)
{
    extern __shared__ float sm[];
    float* Qs = sm;                       // [128][QPAD]
    float* Kbuf = sm + 128 * QPAD;        // 2 x [64][128]
    const int tid = threadIdx.x;
    const int tx = tid & 15, ty = tid >> 4;
    const int bh = blockIdx.z;
    const int i0 = blockIdx.y * 128;
    const int jb0 = blockIdx.x * 4;

    const float* Qp = g_q + ((size_t)bh * SS + i0) * HD;
    const float* Ktp = g_kt + (size_t)bh * HD * SS;

#pragma unroll
    for (int e = 0; e < 8; e++) {
        int f = e * 256 + tid;
        int r = f >> 4, c4 = f & 15;
        cpa16(&Qs[r * QPAD + c4 * 4], Qp + (size_t)r * HD + c4 * 4);
    }
    CPA_COMMIT;

    auto prefetchK = [&](int j0, int buf) {
        float* Ks = Kbuf + buf * KSTAGE;
#pragma unroll
        for (int e = 0; e < 8; e++) {
            int f = e * 256 + tid;
            int d = f >> 5, c = f & 31;
            cpa16(&Ks[d * 128 + c * 4], Ktp + (size_t)d * SS + j0 + c * 4);
        }
        CPA_COMMIT;
    };
    prefetchK(jb0 * 128, 0);

    for (int jt = 0; jt < 4; jt++) {
        const int j0 = (jb0 + jt) * 128;
        if (jt < 3) { prefetchK(j0 + 128, (jt + 1) & 1); CPA_WAIT1; }
        else        { CPA_WAIT0; }
        __syncthreads();
        const float* Ks = Kbuf + (jt & 1) * KSTAGE;

        u64 acc[8][4];
#pragma unroll
        for (int i = 0; i < 8; i++)
#pragma unroll
            for (int j = 0; j < 4; j++) acc[i][j] = 0ull;

#pragma unroll 4
        for (int d4 = 0; d4 < 16; d4++) {
            float4 aq[8];
#pragma unroll
            for (int i = 0; i < 8; i++)
                aq[i] = *(const float4*)&Qs[(ty * 8 + i) * QPAD + d4 * 4];
#pragma unroll
            for (int dd = 0; dd < 4; dd++) {
                const float* bp = &Ks[(d4 * 4 + dd) * 128 + tx * 8];
                ulonglong2 b0 = *(const ulonglong2*)bp;
                ulonglong2 b1 = *(const ulonglong2*)(bp + 4);
#pragma unroll
                for (int i = 0; i < 8; i++) {
                    u64 ap = bcast2(f4c(aq[i], dd));
                    acc[i][0] = ffma2(ap, b0.x, acc[i][0]);
                    acc[i][1] = ffma2(ap, b0.y, acc[i][1]);
                    acc[i][2] = ffma2(ap, b1.x, acc[i][2]);
                    acc[i][3] = ffma2(ap, b1.y, acc[i][3]);
                }
            }
        }

#pragma unroll
        for (int i = 0; i < 8; i++) {
            float2 p0 = unpk(acc[i][0]), p1 = unpk(acc[i][1]);
            float2 p2 = unpk(acc[i][2]), p3 = unpk(acc[i][3]);
            float4 o0 = make_float4(p0.x * 0.25f, p0.y * 0.25f, p1.x * 0.25f, p1.y * 0.25f);
            float4 o1 = make_float4(p2.x * 0.25f, p2.y * 0.25f, p3.x * 0.25f, p3.y * 0.25f);
            float* op = wout + ((size_t)bh * SS + i0 + ty * 8 + i) * SS + j0 + tx * 8;
            *(float4*)op = o0;
            *(float4*)(op + 4) = o1;
        }
        __syncthreads();
    }
}

// ---------------------------------------------------------------------------
// Row softmax + threshold prune + L1 renorm, in place (exact fp32 path).
// One warp per row; 2048 floats in 64 regs/lane.
// ---------------------------------------------------------------------------
__global__ __launch_bounds__(256) void softmax_kernel(
    const unsigned char* __restrict__ mask, float* __restrict__ w)
{
    const int lane = threadIdx.x & 31;
    const size_t row = (size_t)blockIdx.x * 8 + (threadIdx.x >> 5);
    const int b = (int)(row >> 15);
    float4* rp = (float4*)(w + row * SS);
    const uchar4* mp = (const uchar4*)(mask + (size_t)b * SS);

    float x[64];
    float mx = -3.0e38f;
#pragma unroll
    for (int v = 0; v < 16; v++) {
        float4 t = rp[lane + v * 32];
        uchar4 m = mp[lane + v * 32];
        x[v * 4 + 0] = m.x ? -1e30f : t.x;
        x[v * 4 + 1] = m.y ? -1e30f : t.y;
        x[v * 4 + 2] = m.z ? -1e30f : t.z;
        x[v * 4 + 3] = m.w ? -1e30f : t.w;
    }
#pragma unroll
    for (int i = 0; i < 64; i++) mx = fmaxf(mx, x[i]);
#pragma unroll
    for (int o = 16; o; o >>= 1) mx = fmaxf(mx, __shfl_xor_sync(0xffffffffu, mx, o));

    float z = 0.f;
#pragma unroll
    for (int i = 0; i < 64; i++) {
        float e = __expf(x[i] - mx);
        x[i] = e;
        z += e;
    }
#pragma unroll
    for (int o = 16; o; o >>= 1) z += __shfl_xor_sync(0xffffffffu, z, o);

    const float cut = 0.01f * z;
    float sk = 0.f;
#pragma unroll
    for (int i = 0; i < 64; i++)
        if (x[i] >= cut) sk += x[i];
#pragma unroll
    for (int o = 16; o; o >>= 1) sk += __shfl_xor_sync(0xffffffffu, sk, o);
    const float inv = sk > 0.f ? 1.f / sk : 0.f;

#pragma unroll
    for (int v = 0; v < 16; v++) {
        float4 o4;
        o4.x = x[v * 4 + 0] >= cut ? x[v * 4 + 0] * inv : 0.f;
        o4.y = x[v * 4 + 1] >= cut ? x[v * 4 + 1] * inv : 0.f;
        o4.z = x[v * 4 + 2] >= cut ? x[v * 4 + 2] * inv : 0.f;
        o4.w = x[v * 4 + 3] >= cut ? x[v * 4 + 3] * inv : 0.f;
        rp[lane + v * 32] = o4;
    }
}

// ---------------------------------------------------------------------------
// PV GEMM: out[b][s][h*64+d] = sum_j W[bh][i][j] * V[bh][j][d].
// Tile 128(M) x 64(N), k-chunk 32, 8x8 FFMA2 micro-tile, 128 threads,
// 4 CTAs/SM -> grid 512 = single wave. 2-stage cp.async.
// ---------------------------------------------------------------------------
#define WPAD 36
#define PV_STAGE (128 * WPAD + 32 * 64)     // 6656 floats per stage
#define PV_SMEM (2 * PV_STAGE * 4)          // 53.2 KB

__global__ __launch_bounds__(128, 4) void pv_kernel(
    const float* __restrict__ wts, float* __restrict__ outp)
{
    extern __shared__ float psm[];
    const int tid = threadIdx.x;
    const int tx = tid & 7;            // col group (8 cols of 64)
    const int ty = tid >> 3;           // row group (0..15, 8 rows each)
    const int bh = blockIdx.y;
    const int b = bh >> 4, h = bh & 15;
    const int i0 = blockIdx.x * 128;
    const float* Wp = wts + ((size_t)bh * SS + i0) * SS;
    const float* Vp = g_v + (size_t)bh * SS * HD;

    auto prefetch = [&](int kc, int buf) {
        float* Wt = psm + buf * PV_STAGE;
        float* Vt = Wt + 128 * WPAD;
        // W: 128 rows x 32 k = 4096 floats -> 8 cpa16/thread
#pragma unroll
        for (int e = 0; e < 8; e++) {
            int f = e * 128 + tid;
            int r = f >> 3, c4 = f & 7;
            cpa16(&Wt[r * WPAD + c4 * 4], Wp + (size_t)r * SS + kc + c4 * 4);
        }
        // V: 32 j x 64 d = 2048 floats -> 4 cpa16/thread
#pragma unroll
        for (int e = 0; e < 4; e++) {
            int f = e * 128 + tid;
            int j = f >> 4, c4 = f & 15;
            cpa16(&Vt[j * 64 + c4 * 4], Vp + (size_t)(kc + j) * HD + c4 * 4);
        }
        CPA_COMMIT;
    };

    u64 acc[8][4];
#pragma unroll
    for (int i = 0; i < 8; i++)
#pragma unroll
        for (int j = 0; j < 4; j++) acc[i][j] = 0ull;

    prefetch(0, 0);

    for (int it = 0; it < 64; it++) {
        if (it < 63) { prefetch((it + 1) * 32, (it + 1) & 1); CPA_WAIT1; }
        else         { CPA_WAIT0; }
        __syncthreads();
        const float* Wt = psm + (it & 1) * PV_STAGE;
        const float* Vt = Wt + 128 * WPAD;
#pragma unroll
        for (int k4 = 0; k4 < 8; k4++) {
            float4 aw[8];
#pragma unroll
            for (int i = 0; i < 8; i++)
                aw[i] = *(const float4*)&Wt[(ty * 8 + i) * WPAD + k4 * 4];
#pragma unroll
            for (int dd = 0; dd < 4; dd++) {
                const float* bp = &Vt[(k4 * 4 + dd) * 64 + tx * 8];
                ulonglong2 b0 = *(const ulonglong2*)bp;
                ulonglong2 b1 = *(const ulonglong2*)(bp + 4);
#pragma unroll
                for (int i = 0; i < 8; i++) {
                    u64 ap = bcast2(f4c(aw[i], dd));
                    acc[i][0] = ffma2(ap, b0.x, acc[i][0]);
                    acc[i][1] = ffma2(ap, b0.y, acc[i][1]);
                    acc[i][2] = ffma2(ap, b1.x, acc[i][2]);
                    acc[i][3] = ffma2(ap, b1.y, acc[i][3]);
                }
            }
        }
        __syncthreads();
    }

#pragma unroll
    for (int i = 0; i < 8; i++) {
        float2 p0 = unpk(acc[i][0]), p1 = unpk(acc[i][1]);
        float2 p2 = unpk(acc[i][2]), p3 = unpk(acc[i][3]);
        float4 o0 = make_float4(p0.x, p0.y, p1.x, p1.y);
        float4 o1 = make_float4(p2.x, p2.y, p3.x, p3.y);
        int s = i0 + ty * 8 + i;
        float* op = outp + ((size_t)b * SS + s) * HH + h * HD + tx * 8;
        *(float4*)op = o0;
        *(float4*)(op + 4) = o1;
    }
}

// ---------------------------------------------------------------------------
extern "C" void kernel_launch(void* const* d_in, const int* in_sizes, int n_in,
                              void* d_out, int out_size)
{
    const float* query = (const float*)d_in[0];
    const float* key   = (const float*)d_in[1];
    const float* value = (const float*)d_in[2];
    const unsigned char* mask = (const unsigned char*)d_in[3];
    const float* Wq = (const float*)d_in[4];
    const float* bq = (const float*)d_in[5];
    const float* Wk = (const float*)d_in[6];
    const float* bk = (const float*)d_in[7];
    const float* Wv = (const float*)d_in[8];
    const float* bv = (const float*)d_in[9];

    float* outp = (float*)d_out;                        // [B,S,H]
    float* wts  = outp + (size_t)BB * SS * HH;          // [B,h,S,S]

    float *gq, *gk, *gv, *gkt, *gwt;
    cudaGetSymbolAddress((void**)&gq, g_q);
    cudaGetSymbolAddress((void**)&gk, g_k);
    cudaGetSymbolAddress((void**)&gv, g_v);
    cudaGetSymbolAddress((void**)&gkt, g_kt);
    cudaGetSymbolAddress((void**)&gwt, g_wt);

    cudaFuncSetAttribute(proj_kernel, cudaFuncAttributeMaxDynamicSharedMemorySize,
                         PROJ_SMEM);
    cudaFuncSetAttribute(score_kernel, cudaFuncAttributeMaxDynamicSharedMemorySize,
                         SCORE_SMEM);
    cudaFuncSetAttribute(pv_kernel, cudaFuncAttributeMaxDynamicSharedMemorySize,
                         PV_SMEM);

    dim3 tb(32, 8);

    transpose_w3<<<dim3(32, 32, 3), tb>>>(Wq, Wk, Wv, gwt);

    dim3 pgrid(HH / 128, NROWS / 64, 3);
    proj_kernel<<<pgrid, 128, PROJ_SMEM>>>(query, key, value, gwt, bq, bk, bv, gq, gk, gv);

    dim3 tkgrid(SS / 32, HD / 32, BH);
    transpose_k<<<tkgrid, tb>>>(gk, gkt);

    dim3 sgrid(SS / 128 / 4, SS / 128, BH);
    score_kernel<<<sgrid, 256, SCORE_SMEM>>>(wts);

    softmax_kernel<<<(BH * SS) / 8, 256>>>(mask, wts);

    dim3 vgrid(SS / 128, BH);
    pv_kernel<<<vgrid, 128, PV_SMEM>>>(wts, outp);
}

// round 8
// speedup vs baseline: 1.1202x; 1.0337x over previous
#include <cuda_runtime.h>
#include <math.h>
#include <stdint.h>

#define BB 2
#define SS 2048
#define HH 1024
#define NH 16
#define HD 64
#define BH 32
#define NROWS 4096

// scratch (static __device__ arrays; no runtime allocation)
__device__ float g_q[(size_t)BH * SS * HD];
__device__ float g_k[(size_t)BH * SS * HD];
__device__ float g_v[(size_t)BH * SS * HD];
__device__ float g_kt[(size_t)BH * HD * SS];      // K transposed: [bh][d][s]
__device__ float g_wt[3 * (size_t)HH * HH];       // Wq,Wk,Wv transposed: [k][n]

typedef unsigned long long u64;

// ---- packed fp32x2 helpers (sm_103a FFMA2) ----
__device__ __forceinline__ u64 bcast2(float x) {
    u64 d; unsigned int u = __float_as_uint(x);
    asm("mov.b64 %0, {%1,%2};" : "=l"(d) : "r"(u), "r"(u));
    return d;
}
__device__ __forceinline__ u64 ffma2(u64 a, u64 b, u64 c) {
    u64 d;
    asm("fma.rn.f32x2 %0, %1, %2, %3;" : "=l"(d) : "l"(a), "l"(b), "l"(c));
    return d;
}
__device__ __forceinline__ float2 unpk(u64 v) {
    unsigned int lo, hi;
    asm("mov.b64 {%0,%1}, %2;" : "=r"(lo), "=r"(hi) : "l"(v));
    return make_float2(__uint_as_float(lo), __uint_as_float(hi));
}
__device__ __forceinline__ float f4c(const float4& v, int i) {
    return i == 0 ? v.x : i == 1 ? v.y : i == 2 ? v.z : v.w;
}

// ---- cp.async helpers ----
__device__ __forceinline__ void cpa16(void* s, const void* g) {
    unsigned int sa = (unsigned int)__cvta_generic_to_shared(s);
    asm volatile("cp.async.ca.shared.global [%0], [%1], 16;" :: "r"(sa), "l"(g));
}
#define CPA_COMMIT  asm volatile("cp.async.commit_group;")
#define CPA_WAIT1   asm volatile("cp.async.wait_group 1;")
#define CPA_WAIT0   asm volatile("cp.async.wait_group 0;")

// ---------------------------------------------------------------------------
// Transpose all three W matrices: g_wt[z][k][n] = W_z[n][k]
// ---------------------------------------------------------------------------
__global__ __launch_bounds__(256) void transpose_w3(
    const float* __restrict__ Wq, const float* __restrict__ Wk,
    const float* __restrict__ Wv, float* __restrict__ outp)
{
    __shared__ float t[32][33];
    const int z = blockIdx.z;
    const float* in = z == 0 ? Wq : z == 1 ? Wk : Wv;
    float* op = outp + (size_t)z * HH * HH;
    const int x0 = blockIdx.x * 32, y0 = blockIdx.y * 32;
    const int x = threadIdx.x, y = threadIdx.y;   // 32 x 8
    for (int i = y; i < 32; i += 8) t[i][x] = in[(size_t)(y0 + i) * HH + x0 + x];
    __syncthreads();
    for (int i = y; i < 32; i += 8) op[(size_t)(x0 + i) * HH + y0 + x] = t[x][i];
}

// ---------------------------------------------------------------------------
// Transpose K: [bh][s][d] -> [bh][d][s]
// ---------------------------------------------------------------------------
__global__ __launch_bounds__(256) void transpose_k(
    const float* __restrict__ in, float* __restrict__ outp)
{
    __shared__ float t[32][33];
    const int bh = blockIdx.z;
    const int s0 = blockIdx.x * 32;
    const int d0 = blockIdx.y * 32;
    const int x = threadIdx.x, y = threadIdx.y;   // 32 x 8
    const float* ip = in + ((size_t)bh * SS + s0) * HD + d0;
    for (int i = y; i < 32; i += 8) t[i][x] = ip[(size_t)i * HD + x];
    __syncthreads();
    float* op = outp + ((size_t)bh * HD + d0) * SS + s0;
    for (int i = y; i < 32; i += 8) op[(size_t)i * SS + x] = t[x][i];
}

// ---------------------------------------------------------------------------
// Fused QKV projection GEMM (grid.z selects q/k/v): out = X @ W^T + b,
// scattered to [bh][s][d]. Tile 64(M)x128(N), BK=32, 8x8 FFMA2 micro-tile,
// conflict-free split columns {tx*4, tx*4+64}. 128 threads, 4 CTAs/SM.
// ---------------------------------------------------------------------------
#define APAD 36
#define PROJ_STAGE (64 * APAD + 32 * 128)    // 6400 floats per stage
#define PROJ_SMEM (2 * PROJ_STAGE * 4)       // 51.2 KB

__global__ __launch_bounds__(128, 4) void proj_kernel(
    const float* __restrict__ Xq, const float* __restrict__ Xk,
    const float* __restrict__ Xv, const float* __restrict__ Wt3,
    const float* __restrict__ bq, const float* __restrict__ bk,
    const float* __restrict__ bv,
    float* __restrict__ oq, float* __restrict__ ok, float* __restrict__ ov)
{
    extern __shared__ float sm[];
    const int z = blockIdx.z;
    const float* X    = z == 0 ? Xq : z == 1 ? Xk : Xv;
    const float* Wt   = Wt3 + (size_t)z * HH * HH;
    const float* bias = z == 0 ? bq : z == 1 ? bk : bv;
    float* outp       = z == 0 ? oq : z == 1 ? ok : ov;

    const int tid = threadIdx.x;
    const int tx = tid & 15;           // col group: cols {tx*4, tx*4+64}
    const int ty = tid >> 4;           // row group (8 rows), 0..7
    const int i0 = blockIdx.y * 64;
    const int j0 = blockIdx.x * 128;

    auto prefetch = [&](int k0, int buf) {
        float* As = sm + buf * PROJ_STAGE;
        float* Bs = As + 64 * APAD;
#pragma unroll
        for (int e = 0; e < 4; e++) {
            int f = e * 128 + tid;
            int r = f >> 3, c4 = f & 7;
            cpa16(&As[r * APAD + c4 * 4], X + (size_t)(i0 + r) * HH + k0 + c4 * 4);
        }
#pragma unroll
        for (int e = 0; e < 8; e++) {
            int f = e * 128 + tid;
            int k = f >> 5, c = f & 31;
            cpa16(&Bs[k * 128 + c * 4], Wt + (size_t)(k0 + k) * HH + j0 + c * 4);
        }
        CPA_COMMIT;
    };

    u64 acc[8][4];
#pragma unroll
    for (int i = 0; i < 8; i++)
#pragma unroll
        for (int j = 0; j < 4; j++) acc[i][j] = 0ull;

    prefetch(0, 0);

    for (int it = 0; it < 32; it++) {
        if (it < 31) { prefetch((it + 1) * 32, (it + 1) & 1); CPA_WAIT1; }
        else         { CPA_WAIT0; }
        __syncthreads();
        const float* As = sm + (it & 1) * PROJ_STAGE;
        const float* Bs = As + 64 * APAD;
#pragma unroll
        for (int k4 = 0; k4 < 8; k4++) {
            float4 aq[8];
#pragma unroll
            for (int i = 0; i < 8; i++)
                aq[i] = *(const float4*)&As[(ty * 8 + i) * APAD + k4 * 4];
#pragma unroll
            for (int dd = 0; dd < 4; dd++) {
                const float* bp = &Bs[(k4 * 4 + dd) * 128 + tx * 4];
                ulonglong2 b0 = *(const ulonglong2*)bp;         // cols tx*4..+3
                ulonglong2 b1 = *(const ulonglong2*)(bp + 64);  // cols 64+tx*4..+3
#pragma unroll
                for (int i = 0; i < 8; i++) {
                    u64 ap = bcast2(f4c(aq[i], dd));
                    acc[i][0] = ffma2(ap, b0.x, acc[i][0]);
                    acc[i][1] = ffma2(ap, b0.y, acc[i][1]);
                    acc[i][2] = ffma2(ap, b1.x, acc[i][2]);
                    acc[i][3] = ffma2(ap, b1.y, acc[i][3]);
                }
            }
        }
        __syncthreads();
    }

    const int col0 = j0 + tx * 4;          // first half (head h0)
    const int col1 = col0 + 64;            // second half (head h0+1)
    const int h0 = col0 >> 6, d0 = col0 & 63;
    const int h1 = col1 >> 6, d1 = col1 & 63;
    float4 bb0 = *(const float4*)(bias + col0);
    float4 bb1 = *(const float4*)(bias + col1);
#pragma unroll
    for (int i = 0; i < 8; i++) {
        int r = i0 + ty * 8 + i;
        int b = r >> 11, s = r & 2047;
        float2 p0 = unpk(acc[i][0]), p1 = unpk(acc[i][1]);
        float2 p2 = unpk(acc[i][2]), p3 = unpk(acc[i][3]);
        float4 o0 = make_float4(p0.x + bb0.x, p0.y + bb0.y, p1.x + bb0.z, p1.y + bb0.w);
        float4 o1 = make_float4(p2.x + bb1.x, p2.y + bb1.y, p3.x + bb1.z, p3.y + bb1.w);
        *(float4*)(outp + (((size_t)(b * NH + h0)) * SS + s) * HD + d0) = o0;
        *(float4*)(outp + (((size_t)(b * NH + h1)) * SS + s) * HD + d1) = o1;
    }
}

// ---------------------------------------------------------------------------
// Score GEMM: wout[bh][i][j] = 0.25 * sum_d q[i,d]*k[j,d].
// Block = 128 i-rows x (4 consecutive 128-wide j-tiles). Conflict-free split
// columns {tx*4, tx*4+64}. Q loaded once, K^T double-buffered. 2 CTAs/SM.
// ---------------------------------------------------------------------------
#define QPAD 68
#define KSTAGE (64 * 128)
#define SCORE_SMEM ((128 * QPAD + 2 * KSTAGE) * 4)

__global__ __launch_bounds__(256, 2) void score_kernel(float* __restrict__ wout)
{
    extern __shared__ float sm[];
    float* Qs = sm;                       // [128][QPAD]
    float* Kbuf = sm + 128 * QPAD;        // 2 x [64][128]
    const int tid = threadIdx.x;
    const int tx = tid & 15, ty = tid >> 4;
    const int bh = blockIdx.z;
    const int i0 = blockIdx.y * 128;
    const int jb0 = blockIdx.x * 4;

    const float* Qp = g_q + ((size_t)bh * SS + i0) * HD;
    const float* Ktp = g_kt + (size_t)bh * HD * SS;

#pragma unroll
    for (int e = 0; e < 8; e++) {
        int f = e * 256 + tid;
        int r = f >> 4, c4 = f & 15;
        cpa16(&Qs[r * QPAD + c4 * 4], Qp + (size_t)r * HD + c4 * 4);
    }
    CPA_COMMIT;

    auto prefetchK = [&](int j0, int buf) {
        float* Ks = Kbuf + buf * KSTAGE;
#pragma unroll
        for (int e = 0; e < 8; e++) {
            int f = e * 256 + tid;
            int d = f >> 5, c = f & 31;
            cpa16(&Ks[d * 128 + c * 4], Ktp + (size_t)d * SS + j0 + c * 4);
        }
        CPA_COMMIT;
    };
    prefetchK(jb0 * 128, 0);

    for (int jt = 0; jt < 4; jt++) {
        const int j0 = (jb0 + jt) * 128;
        if (jt < 3) { prefetchK(j0 + 128, (jt + 1) & 1); CPA_WAIT1; }
        else        { CPA_WAIT0; }
        __syncthreads();
        const float* Ks = Kbuf + (jt & 1) * KSTAGE;

        u64 acc[8][4];
#pragma unroll
        for (int i = 0; i < 8; i++)
#pragma unroll
            for (int j = 0; j < 4; j++) acc[i][j] = 0ull;

#pragma unroll 4
        for (int d4 = 0; d4 < 16; d4++) {
            float4 aq[8];
#pragma unroll
            for (int i = 0; i < 8; i++)
                aq[i] = *(const float4*)&Qs[(ty * 8 + i) * QPAD + d4 * 4];
#pragma unroll
            for (int dd = 0; dd < 4; dd++) {
                const float* bp = &Ks[(d4 * 4 + dd) * 128 + tx * 4];
                ulonglong2 b0 = *(const ulonglong2*)bp;         // cols tx*4..+3
                ulonglong2 b1 = *(const ulonglong2*)(bp + 64);  // cols 64+tx*4..+3
#pragma unroll
                for (int i = 0; i < 8; i++) {
                    u64 ap = bcast2(f4c(aq[i], dd));
                    acc[i][0] = ffma2(ap, b0.x, acc[i][0]);
                    acc[i][1] = ffma2(ap, b0.y, acc[i][1]);
                    acc[i][2] = ffma2(ap, b1.x, acc[i][2]);
                    acc[i][3] = ffma2(ap, b1.y, acc[i][3]);
                }
            }
        }

#pragma unroll
        for (int i = 0; i < 8; i++) {
            float2 p0 = unpk(acc[i][0]), p1 = unpk(acc[i][1]);
            float2 p2 = unpk(acc[i][2]), p3 = unpk(acc[i][3]);
            float4 o0 = make_float4(p0.x * 0.25f, p0.y * 0.25f, p1.x * 0.25f, p1.y * 0.25f);
            float4 o1 = make_float4(p2.x * 0.25f, p2.y * 0.25f, p3.x * 0.25f, p3.y * 0.25f);
            float* op = wout + ((size_t)bh * SS + i0 + ty * 8 + i) * SS + j0 + tx * 4;
            *(float4*)op = o0;
            *(float4*)(op + 64) = o1;
        }
        __syncthreads();
    }
}

// ---------------------------------------------------------------------------
// Row softmax + threshold prune + L1 renorm, in place (exact fp32 path).
// One warp per row; 2048 floats in 64 regs/lane.
// ---------------------------------------------------------------------------
__global__ __launch_bounds__(256) void softmax_kernel(
    const unsigned char* __restrict__ mask, float* __restrict__ w)
{
    const int lane = threadIdx.x & 31;
    const size_t row = (size_t)blockIdx.x * 8 + (threadIdx.x >> 5);
    const int b = (int)(row >> 15);
    float4* rp = (float4*)(w + row * SS);
    const uchar4* mp = (const uchar4*)(mask + (size_t)b * SS);

    float x[64];
    float mx = -3.0e38f;
#pragma unroll
    for (int v = 0; v < 16; v++) {
        float4 t = rp[lane + v * 32];
        uchar4 m = mp[lane + v * 32];
        x[v * 4 + 0] = m.x ? -1e30f : t.x;
        x[v * 4 + 1] = m.y ? -1e30f : t.y;
        x[v * 4 + 2] = m.z ? -1e30f : t.z;
        x[v * 4 + 3] = m.w ? -1e30f : t.w;
    }
#pragma unroll
    for (int i = 0; i < 64; i++) mx = fmaxf(mx, x[i]);
#pragma unroll
    for (int o = 16; o; o >>= 1) mx = fmaxf(mx, __shfl_xor_sync(0xffffffffu, mx, o));

    float z = 0.f;
#pragma unroll
    for (int i = 0; i < 64; i++) {
        float e = __expf(x[i] - mx);
        x[i] = e;
        z += e;
    }
#pragma unroll
    for (int o = 16; o; o >>= 1) z += __shfl_xor_sync(0xffffffffu, z, o);

    const float cut = 0.01f * z;
    float sk = 0.f;
#pragma unroll
    for (int i = 0; i < 64; i++)
        if (x[i] >= cut) sk += x[i];
#pragma unroll
    for (int o = 16; o; o >>= 1) sk += __shfl_xor_sync(0xffffffffu, sk, o);
    const float inv = sk > 0.f ? 1.f / sk : 0.f;

#pragma unroll
    for (int v = 0; v < 16; v++) {
        float4 o4;
        o4.x = x[v * 4 + 0] >= cut ? x[v * 4 + 0] * inv : 0.f;
        o4.y = x[v * 4 + 1] >= cut ? x[v * 4 + 1] * inv : 0.f;
        o4.z = x[v * 4 + 2] >= cut ? x[v * 4 + 2] * inv : 0.f;
        o4.w = x[v * 4 + 3] >= cut ? x[v * 4 + 3] * inv : 0.f;
        rp[lane + v * 32] = o4;
    }
}

// ---------------------------------------------------------------------------
// PV GEMM: out[b][s][h*64+d] = sum_j W[bh][i][j] * V[bh][j][d].
// Tile 128(M) x 64(N), k-chunk 32, 8x8 micro, conflict-free split columns
// {tx*4, tx*4+32}. 128 threads, 4 CTAs/SM.
// ---------------------------------------------------------------------------
#define WPAD 36
#define PV_STAGE (128 * WPAD + 32 * 64)     // 6656 floats per stage
#define PV_SMEM (2 * PV_STAGE * 4)          // 53.2 KB

__global__ __launch_bounds__(128, 4) void pv_kernel(
    const float* __restrict__ wts, float* __restrict__ outp)
{
    extern __shared__ float psm[];
    const int tid = threadIdx.x;
    const int tx = tid & 7;            // col group: cols {tx*4, tx*4+32}
    const int ty = tid >> 3;           // row group (0..15, 8 rows each)
    const int bh = blockIdx.y;
    const int b = bh >> 4, h = bh & 15;
    const int i0 = blockIdx.x * 128;
    const float* Wp = wts + ((size_t)bh * SS + i0) * SS;
    const float* Vp = g_v + (size_t)bh * SS * HD;

    auto prefetch = [&](int kc, int buf) {
        float* Wt = psm + buf * PV_STAGE;
        float* Vt = Wt + 128 * WPAD;
#pragma unroll
        for (int e = 0; e < 8; e++) {
            int f = e * 128 + tid;
            int r = f >> 3, c4 = f & 7;
            cpa16(&Wt[r * WPAD + c4 * 4], Wp + (size_t)r * SS + kc + c4 * 4);
        }
#pragma unroll
        for (int e = 0; e < 4; e++) {
            int f = e * 128 + tid;
            int j = f >> 4, c4 = f & 15;
            cpa16(&Vt[j * 64 + c4 * 4], Vp + (size_t)(kc + j) * HD + c4 * 4);
        }
        CPA_COMMIT;
    };

    u64 acc[8][4];
#pragma unroll
    for (int i = 0; i < 8; i++)
#pragma unroll
        for (int j = 0; j < 4; j++) acc[i][j] = 0ull;

    prefetch(0, 0);

    for (int it = 0; it < 64; it++) {
        if (it < 63) { prefetch((it + 1) * 32, (it + 1) & 1); CPA_WAIT1; }
        else         { CPA_WAIT0; }
        __syncthreads();
        const float* Wt = psm + (it & 1) * PV_STAGE;
        const float* Vt = Wt + 128 * WPAD;
#pragma unroll
        for (int k4 = 0; k4 < 8; k4++) {
            float4 aw[8];
#pragma unroll
            for (int i = 0; i < 8; i++)
                aw[i] = *(const float4*)&Wt[(ty * 8 + i) * WPAD + k4 * 4];
#pragma unroll
            for (int dd = 0; dd < 4; dd++) {
                const float* bp = &Vt[(k4 * 4 + dd) * 64 + tx * 4];
                ulonglong2 b0 = *(const ulonglong2*)bp;         // cols tx*4..+3
                ulonglong2 b1 = *(const ulonglong2*)(bp + 32);  // cols 32+tx*4..+3
#pragma unroll
                for (int i = 0; i < 8; i++) {
                    u64 ap = bcast2(f4c(aw[i], dd));
                    acc[i][0] = ffma2(ap, b0.x, acc[i][0]);
                    acc[i][1] = ffma2(ap, b0.y, acc[i][1]);
                    acc[i][2] = ffma2(ap, b1.x, acc[i][2]);
                    acc[i][3] = ffma2(ap, b1.y, acc[i][3]);
                }
            }
        }
        __syncthreads();
    }

#pragma unroll
    for (int i = 0; i < 8; i++) {
        float2 p0 = unpk(acc[i][0]), p1 = unpk(acc[i][1]);
        float2 p2 = unpk(acc[i][2]), p3 = unpk(acc[i][3]);
        float4 o0 = make_float4(p0.x, p0.y, p1.x, p1.y);
        float4 o1 = make_float4(p2.x, p2.y, p3.x, p3.y);
        int s = i0 + ty * 8 + i;
        float* op = outp + ((size_t)b * SS + s) * HH + h * HD + tx * 4;
        *(float4*)op = o0;
        *(float4*)(op + 32) = o1;
    }
}

// ---------------------------------------------------------------------------
extern "C" void kernel_launch(void* const* d_in, const int* in_sizes, int n_in,
                              void* d_out, int out_size)
{
    const float* query = (const float*)d_in[0];
    const float* key   = (const float*)d_in[1];
    const float* value = (const float*)d_in[2];
    const unsigned char* mask = (const unsigned char*)d_in[3];
    const float* Wq = (const float*)d_in[4];
    const float* bq = (const float*)d_in[5];
    const float* Wk = (const float*)d_in[6];
    const float* bk = (const float*)d_in[7];
    const float* Wv = (const float*)d_in[8];
    const float* bv = (const float*)d_in[9];

    float* outp = (float*)d_out;                        // [B,S,H]
    float* wts  = outp + (size_t)BB * SS * HH;          // [B,h,S,S]

    float *gq, *gk, *gv, *gkt, *gwt;
    cudaGetSymbolAddress((void**)&gq, g_q);
    cudaGetSymbolAddress((void**)&gk, g_k);
    cudaGetSymbolAddress((void**)&gv, g_v);
    cudaGetSymbolAddress((void**)&gkt, g_kt);
    cudaGetSymbolAddress((void**)&gwt, g_wt);

    cudaFuncSetAttribute(proj_kernel, cudaFuncAttributeMaxDynamicSharedMemorySize,
                         PROJ_SMEM);
    cudaFuncSetAttribute(score_kernel, cudaFuncAttributeMaxDynamicSharedMemorySize,
                         SCORE_SMEM);
    cudaFuncSetAttribute(pv_kernel, cudaFuncAttributeMaxDynamicSharedMemorySize,
                         PV_SMEM);

    dim3 tb(32, 8);

    transpose_w3<<<dim3(32, 32, 3), tb>>>(Wq, Wk, Wv, gwt);

    dim3 pgrid(HH / 128, NROWS / 64, 3);
    proj_kernel<<<pgrid, 128, PROJ_SMEM>>>(query, key, value, gwt, bq, bk, bv, gq, gk, gv);

    dim3 tkgrid(SS / 32, HD / 32, BH);
    transpose_k<<<tkgrid, tb>>>(gk, gkt);

    dim3 sgrid(SS / 128 / 4, SS / 128, BH);
    score_kernel<<<sgrid, 256, SCORE_SMEM>>>(wts);

    softmax_kernel<<<(BH * SS) / 8, 256>>>(mask, wts);

    dim3 vgrid(SS / 128, BH);
    pv_kernel<<<vgrid, 128, PV_SMEM>>>(wts, outp);
}

// round 9
// speedup vs baseline: 1.1492x; 1.0259x over previous
#include <cuda_runtime.h>
#include <math.h>
#include <stdint.h>

#define BB 2
#define SS 2048
#define HH 1024
#define NH 16
#define HD 64
#define BH 32
#define NROWS 4096

// scratch (static __device__ arrays; no runtime allocation)
__device__ float g_q[(size_t)BH * SS * HD];
__device__ float g_k[(size_t)BH * SS * HD];
__device__ float g_v[(size_t)BH * SS * HD];
__device__ float g_kt[(size_t)BH * HD * SS];      // K transposed: [bh][d][s]
__device__ float g_wt[3 * (size_t)HH * HH];       // Wq,Wk,Wv transposed: [k][n]

typedef unsigned long long u64;

// ---- packed fp32x2 helpers (sm_103a FFMA2) ----
__device__ __forceinline__ u64 bcast2(float x) {
    u64 d; unsigned int u = __float_as_uint(x);
    asm("mov.b64 %0, {%1,%2};" : "=l"(d) : "r"(u), "r"(u));
    return d;
}
__device__ __forceinline__ u64 ffma2(u64 a, u64 b, u64 c) {
    u64 d;
    asm("fma.rn.f32x2 %0, %1, %2, %3;" : "=l"(d) : "l"(a), "l"(b), "l"(c));
    return d;
}
__device__ __forceinline__ float2 unpk(u64 v) {
    unsigned int lo, hi;
    asm("mov.b64 {%0,%1}, %2;" : "=r"(lo), "=r"(hi) : "l"(v));
    return make_float2(__uint_as_float(lo), __uint_as_float(hi));
}
__device__ __forceinline__ float f4c(const float4& v, int i) {
    return i == 0 ? v.x : i == 1 ? v.y : i == 2 ? v.z : v.w;
}

// ---- cp.async helpers ----
__device__ __forceinline__ void cpa16(void* s, const void* g) {
    unsigned int sa = (unsigned int)__cvta_generic_to_shared(s);
    asm volatile("cp.async.ca.shared.global [%0], [%1], 16;" :: "r"(sa), "l"(g));
}
#define CPA_COMMIT  asm volatile("cp.async.commit_group;")
#define CPA_WAIT1   asm volatile("cp.async.wait_group 1;")
#define CPA_WAIT0   asm volatile("cp.async.wait_group 0;")

// ---------------------------------------------------------------------------
// Transpose all three W matrices: g_wt[z][k][n] = W_z[n][k]
// ---------------------------------------------------------------------------
__global__ __launch_bounds__(256) void transpose_w3(
    const float* __restrict__ Wq, const float* __restrict__ Wk,
    const float* __restrict__ Wv, float* __restrict__ outp)
{
    __shared__ float t[32][33];
    const int z = blockIdx.z;
    const float* in = z == 0 ? Wq : z == 1 ? Wk : Wv;
    float* op = outp + (size_t)z * HH * HH;
    const int x0 = blockIdx.x * 32, y0 = blockIdx.y * 32;
    const int x = threadIdx.x, y = threadIdx.y;   // 32 x 8
    for (int i = y; i < 32; i += 8) t[i][x] = in[(size_t)(y0 + i) * HH + x0 + x];
    __syncthreads();
    for (int i = y; i < 32; i += 8) op[(size_t)(x0 + i) * HH + y0 + x] = t[x][i];
}

// ---------------------------------------------------------------------------
// Transpose K: [bh][s][d] -> [bh][d][s]
// ---------------------------------------------------------------------------
__global__ __launch_bounds__(256) void transpose_k(
    const float* __restrict__ in, float* __restrict__ outp)
{
    __shared__ float t[32][33];
    const int bh = blockIdx.z;
    const int s0 = blockIdx.x * 32;
    const int d0 = blockIdx.y * 32;
    const int x = threadIdx.x, y = threadIdx.y;   // 32 x 8
    const float* ip = in + ((size_t)bh * SS + s0) * HD + d0;
    for (int i = y; i < 32; i += 8) t[i][x] = ip[(size_t)i * HD + x];
    __syncthreads();
    float* op = outp + ((size_t)bh * HD + d0) * SS + s0;
    for (int i = y; i < 32; i += 8) op[(size_t)i * SS + x] = t[x][i];
}

// ---------------------------------------------------------------------------
// Fused QKV projection GEMM (grid.z selects q/k/v): out = X @ W^T + b,
// scattered to [bh][s][d]. Tile 64(M)x128(N), BK=32, 4x16 FFMA2 micro-tile
// (rows i*16+ty, cols tx*4+{0,32,64,96}). 128 threads, 4 CTAs/SM.
// ---------------------------------------------------------------------------
#define APAD 36
#define PROJ_STAGE (64 * APAD + 32 * 128)    // 6400 floats per stage
#define PROJ_SMEM (2 * PROJ_STAGE * 4)       // 51.2 KB

__global__ __launch_bounds__(128, 4) void proj_kernel(
    const float* __restrict__ Xq, const float* __restrict__ Xk,
    const float* __restrict__ Xv, const float* __restrict__ Wt3,
    const float* __restrict__ bq, const float* __restrict__ bk,
    const float* __restrict__ bv,
    float* __restrict__ oq, float* __restrict__ ok, float* __restrict__ ov)
{
    extern __shared__ float sm[];
    const int z = blockIdx.z;
    const float* X    = z == 0 ? Xq : z == 1 ? Xk : Xv;
    const float* Wt   = Wt3 + (size_t)z * HH * HH;
    const float* bias = z == 0 ? bq : z == 1 ? bk : bv;
    float* outp       = z == 0 ? oq : z == 1 ? ok : ov;

    const int tid = threadIdx.x;
    const int tx = tid & 7;            // col base tx*4, chunks +0,+32,+64,+96
    const int ty = tid >> 3;           // 0..15; rows i*16+ty
    const int i0 = blockIdx.y * 64;
    const int j0 = blockIdx.x * 128;

    auto prefetch = [&](int k0, int buf) {
        float* As = sm + buf * PROJ_STAGE;
        float* Bs = As + 64 * APAD;
#pragma unroll
        for (int e = 0; e < 4; e++) {
            int f = e * 128 + tid;
            int r = f >> 3, c4 = f & 7;
            cpa16(&As[r * APAD + c4 * 4], X + (size_t)(i0 + r) * HH + k0 + c4 * 4);
        }
#pragma unroll
        for (int e = 0; e < 8; e++) {
            int f = e * 128 + tid;
            int k = f >> 5, c = f & 31;
            cpa16(&Bs[k * 128 + c * 4], Wt + (size_t)(k0 + k) * HH + j0 + c * 4);
        }
        CPA_COMMIT;
    };

    u64 acc[4][8];
#pragma unroll
    for (int i = 0; i < 4; i++)
#pragma unroll
        for (int j = 0; j < 8; j++) acc[i][j] = 0ull;

    prefetch(0, 0);

    for (int it = 0; it < 32; it++) {
        if (it < 31) { prefetch((it + 1) * 32, (it + 1) & 1); CPA_WAIT1; }
        else         { CPA_WAIT0; }
        __syncthreads();
        const float* As = sm + (it & 1) * PROJ_STAGE;
        const float* Bs = As + 64 * APAD;
#pragma unroll
        for (int k4 = 0; k4 < 8; k4++) {
            float4 aq[4];
#pragma unroll
            for (int i = 0; i < 4; i++)
                aq[i] = *(const float4*)&As[(i * 16 + ty) * APAD + k4 * 4];
#pragma unroll
            for (int dd = 0; dd < 4; dd++) {
                const float* bp = &Bs[(k4 * 4 + dd) * 128 + tx * 4];
                ulonglong2 b0 = *(const ulonglong2*)bp;
                ulonglong2 b1 = *(const ulonglong2*)(bp + 32);
                ulonglong2 b2 = *(const ulonglong2*)(bp + 64);
                ulonglong2 b3 = *(const ulonglong2*)(bp + 96);
#pragma unroll
                for (int i = 0; i < 4; i++) {
                    u64 ap = bcast2(f4c(aq[i], dd));
                    acc[i][0] = ffma2(ap, b0.x, acc[i][0]);
                    acc[i][1] = ffma2(ap, b0.y, acc[i][1]);
                    acc[i][2] = ffma2(ap, b1.x, acc[i][2]);
                    acc[i][3] = ffma2(ap, b1.y, acc[i][3]);
                    acc[i][4] = ffma2(ap, b2.x, acc[i][4]);
                    acc[i][5] = ffma2(ap, b2.y, acc[i][5]);
                    acc[i][6] = ffma2(ap, b3.x, acc[i][6]);
                    acc[i][7] = ffma2(ap, b3.y, acc[i][7]);
                }
            }
        }
        __syncthreads();
    }

#pragma unroll
    for (int c = 0; c < 4; c++) {
        const int col = j0 + tx * 4 + c * 32;
        const int h = col >> 6, d = col & 63;
        float4 bb = *(const float4*)(bias + col);
#pragma unroll
        for (int i = 0; i < 4; i++) {
            int r = i0 + i * 16 + ty;
            int b = r >> 11, s = r & 2047;
            float2 p0 = unpk(acc[i][c * 2]), p1 = unpk(acc[i][c * 2 + 1]);
            float4 o4 = make_float4(p0.x + bb.x, p0.y + bb.y, p1.x + bb.z, p1.y + bb.w);
            *(float4*)(outp + (((size_t)(b * NH + h)) * SS + s) * HD + d) = o4;
        }
    }
}

// ---------------------------------------------------------------------------
// Score GEMM: wout[bh][i][j] = 0.25 * sum_d q[i,d]*k[j,d].
// Block = 128 i-rows x (4 consecutive 128-wide j-tiles). 4x16 micro-tile
// (rows i*32+ty, cols tx*4+{0,32,64,96}). 2 CTAs/SM (128-reg cap).
// ---------------------------------------------------------------------------
#define QPAD 68
#define KSTAGE (64 * 128)
#define SCORE_SMEM ((128 * QPAD + 2 * KSTAGE) * 4)

__global__ __launch_bounds__(256, 2) void score_kernel(float* __restrict__ wout)
{
    extern __shared__ float sm[];
    float* Qs = sm;                       // [128][QPAD]
    float* Kbuf = sm + 128 * QPAD;        // 2 x [64][128]
    const int tid = threadIdx.x;
    const int tx = tid & 7;               // col base tx*4, chunks +0,+32,+64,+96
    const int ty = tid >> 3;              // 0..31; rows i*32+ty
    const int bh = blockIdx.z;
    const int i0 = blockIdx.y * 128;
    const int jb0 = blockIdx.x * 4;

    const float* Qp = g_q + ((size_t)bh * SS + i0) * HD;
    const float* Ktp = g_kt + (size_t)bh * HD * SS;

#pragma unroll
    for (int e = 0; e < 8; e++) {
        int f = e * 256 + tid;
        int r = f >> 4, c4 = f & 15;
        cpa16(&Qs[r * QPAD + c4 * 4], Qp + (size_t)r * HD + c4 * 4);
    }
    CPA_COMMIT;

    auto prefetchK = [&](int j0, int buf) {
        float* Ks = Kbuf + buf * KSTAGE;
#pragma unroll
        for (int e = 0; e < 8; e++) {
            int f = e * 256 + tid;
            int d = f >> 5, c = f & 31;
            cpa16(&Ks[d * 128 + c * 4], Ktp + (size_t)d * SS + j0 + c * 4);
        }
        CPA_COMMIT;
    };
    prefetchK(jb0 * 128, 0);

    for (int jt = 0; jt < 4; jt++) {
        const int j0 = (jb0 + jt) * 128;
        if (jt < 3) { prefetchK(j0 + 128, (jt + 1) & 1); CPA_WAIT1; }
        else        { CPA_WAIT0; }
        __syncthreads();
        const float* Ks = Kbuf + (jt & 1) * KSTAGE;

        u64 acc[4][8];
#pragma unroll
        for (int i = 0; i < 4; i++)
#pragma unroll
            for (int j = 0; j < 8; j++) acc[i][j] = 0ull;

#pragma unroll 4
        for (int d4 = 0; d4 < 16; d4++) {
            float4 aq[4];
#pragma unroll
            for (int i = 0; i < 4; i++)
                aq[i] = *(const float4*)&Qs[(i * 32 + ty) * QPAD + d4 * 4];
#pragma unroll
            for (int dd = 0; dd < 4; dd++) {
                const float* bp = &Ks[(d4 * 4 + dd) * 128 + tx * 4];
                ulonglong2 b0 = *(const ulonglong2*)bp;
                ulonglong2 b1 = *(const ulonglong2*)(bp + 32);
                ulonglong2 b2 = *(const ulonglong2*)(bp + 64);
                ulonglong2 b3 = *(const ulonglong2*)(bp + 96);
#pragma unroll
                for (int i = 0; i < 4; i++) {
                    u64 ap = bcast2(f4c(aq[i], dd));
                    acc[i][0] = ffma2(ap, b0.x, acc[i][0]);
                    acc[i][1] = ffma2(ap, b0.y, acc[i][1]);
                    acc[i][2] = ffma2(ap, b1.x, acc[i][2]);
                    acc[i][3] = ffma2(ap, b1.y, acc[i][3]);
                    acc[i][4] = ffma2(ap, b2.x, acc[i][4]);
                    acc[i][5] = ffma2(ap, b2.y, acc[i][5]);
                    acc[i][6] = ffma2(ap, b3.x, acc[i][6]);
                    acc[i][7] = ffma2(ap, b3.y, acc[i][7]);
                }
            }
        }

#pragma unroll
        for (int i = 0; i < 4; i++) {
            float* op = wout + ((size_t)bh * SS + i0 + i * 32 + ty) * SS + j0 + tx * 4;
#pragma unroll
            for (int c = 0; c < 4; c++) {
                float2 p0 = unpk(acc[i][c * 2]), p1 = unpk(acc[i][c * 2 + 1]);
                float4 o4 = make_float4(p0.x * 0.25f, p0.y * 0.25f,
                                        p1.x * 0.25f, p1.y * 0.25f);
                *(float4*)(op + c * 32) = o4;
            }
        }
        __syncthreads();
    }
}

// ---------------------------------------------------------------------------
// Row softmax + threshold prune + L1 renorm, in place (exact fp32 path).
// One warp per row; 2048 floats in 64 regs/lane.
// ---------------------------------------------------------------------------
__global__ __launch_bounds__(256) void softmax_kernel(
    const unsigned char* __restrict__ mask, float* __restrict__ w)
{
    const int lane = threadIdx.x & 31;
    const size_t row = (size_t)blockIdx.x * 8 + (threadIdx.x >> 5);
    const int b = (int)(row >> 15);
    float4* rp = (float4*)(w + row * SS);
    const uchar4* mp = (const uchar4*)(mask + (size_t)b * SS);

    float x[64];
    float mx = -3.0e38f;
#pragma unroll
    for (int v = 0; v < 16; v++) {
        float4 t = rp[lane + v * 32];
        uchar4 m = mp[lane + v * 32];
        x[v * 4 + 0] = m.x ? -1e30f : t.x;
        x[v * 4 + 1] = m.y ? -1e30f : t.y;
        x[v * 4 + 2] = m.z ? -1e30f : t.z;
        x[v * 4 + 3] = m.w ? -1e30f : t.w;
    }
#pragma unroll
    for (int i = 0; i < 64; i++) mx = fmaxf(mx, x[i]);
#pragma unroll
    for (int o = 16; o; o >>= 1) mx = fmaxf(mx, __shfl_xor_sync(0xffffffffu, mx, o));

    float z = 0.f;
#pragma unroll
    for (int i = 0; i < 64; i++) {
        float e = __expf(x[i] - mx);
        x[i] = e;
        z += e;
    }
#pragma unroll
    for (int o = 16; o; o >>= 1) z += __shfl_xor_sync(0xffffffffu, z, o);

    const float cut = 0.01f * z;
    float sk = 0.f;
#pragma unroll
    for (int i = 0; i < 64; i++)
        if (x[i] >= cut) sk += x[i];
#pragma unroll
    for (int o = 16; o; o >>= 1) sk += __shfl_xor_sync(0xffffffffu, sk, o);
    const float inv = sk > 0.f ? 1.f / sk : 0.f;

#pragma unroll
    for (int v = 0; v < 16; v++) {
        float4 o4;
        o4.x = x[v * 4 + 0] >= cut ? x[v * 4 + 0] * inv : 0.f;
        o4.y = x[v * 4 + 1] >= cut ? x[v * 4 + 1] * inv : 0.f;
        o4.z = x[v * 4 + 2] >= cut ? x[v * 4 + 2] * inv : 0.f;
        o4.w = x[v * 4 + 3] >= cut ? x[v * 4 + 3] * inv : 0.f;
        rp[lane + v * 32] = o4;
    }
}

// ---------------------------------------------------------------------------
// PV GEMM: out[b][s][h*64+d] = sum_j W[bh][i][j] * V[bh][j][d].
// Tile 128(M) x 64(N), k-chunk 32, 4x16 micro-tile (rows i*32+ty,
// cols tx*4+{0,16,32,48}). 128 threads, 4 CTAs/SM.
// ---------------------------------------------------------------------------
#define WPAD 36
#define PV_STAGE (128 * WPAD + 32 * 64)     // 6656 floats per stage
#define PV_SMEM (2 * PV_STAGE * 4)          // 53.2 KB

__global__ __launch_bounds__(128, 4) void pv_kernel(
    const float* __restrict__ wts, float* __restrict__ outp)
{
    extern __shared__ float psm[];
    const int tid = threadIdx.x;
    const int tx = tid & 3;            // col base tx*4, chunks +0,+16,+32,+48
    const int ty = tid >> 2;           // 0..31; rows i*32+ty
    const int bh = blockIdx.y;
    const int b = bh >> 4, h = bh & 15;
    const int i0 = blockIdx.x * 128;
    const float* Wp = wts + ((size_t)bh * SS + i0) * SS;
    const float* Vp = g_v + (size_t)bh * SS * HD;

    auto prefetch = [&](int kc, int buf) {
        float* Wt = psm + buf * PV_STAGE;
        float* Vt = Wt + 128 * WPAD;
#pragma unroll
        for (int e = 0; e < 8; e++) {
            int f = e * 128 + tid;
            int r = f >> 3, c4 = f & 7;
            cpa16(&Wt[r * WPAD + c4 * 4], Wp + (size_t)r * SS + kc + c4 * 4);
        }
#pragma unroll
        for (int e = 0; e < 4; e++) {
            int f = e * 128 + tid;
            int j = f >> 4, c4 = f & 15;
            cpa16(&Vt[j * 64 + c4 * 4], Vp + (size_t)(kc + j) * HD + c4 * 4);
        }
        CPA_COMMIT;
    };

    u64 acc[4][8];
#pragma unroll
    for (int i = 0; i < 4; i++)
#pragma unroll
        for (int j = 0; j < 8; j++) acc[i][j] = 0ull;

    prefetch(0, 0);

    for (int it = 0; it < 64; it++) {
        if (it < 63) { prefetch((it + 1) * 32, (it + 1) & 1); CPA_WAIT1; }
        else         { CPA_WAIT0; }
        __syncthreads();
        const float* Wt = psm + (it & 1) * PV_STAGE;
        const float* Vt = Wt + 128 * WPAD;
#pragma unroll
        for (int k4 = 0; k4 < 8; k4++) {
            float4 aw[4];
#pragma unroll
            for (int i = 0; i < 4; i++)
                aw[i] = *(const float4*)&Wt[(i * 32 + ty) * WPAD + k4 * 4];
#pragma unroll
            for (int dd = 0; dd < 4; dd++) {
                const float* bp = &Vt[(k4 * 4 + dd) * 64 + tx * 4];
                ulonglong2 b0 = *(const ulonglong2*)bp;
                ulonglong2 b1 = *(const ulonglong2*)(bp + 16);
                ulonglong2 b2 = *(const ulonglong2*)(bp + 32);
                ulonglong2 b3 = *(const ulonglong2*)(bp + 48);
#pragma unroll
                for (int i = 0; i < 4; i++) {
                    u64 ap = bcast2(f4c(aw[i], dd));
                    acc[i][0] = ffma2(ap, b0.x, acc[i][0]);
                    acc[i][1] = ffma2(ap, b0.y, acc[i][1]);
                    acc[i][2] = ffma2(ap, b1.x, acc[i][2]);
                    acc[i][3] = ffma2(ap, b1.y, acc[i][3]);
                    acc[i][4] = ffma2(ap, b2.x, acc[i][4]);
                    acc[i][5] = ffma2(ap, b2.y, acc[i][5]);
                    acc[i][6] = ffma2(ap, b3.x, acc[i][6]);
                    acc[i][7] = ffma2(ap, b3.y, acc[i][7]);
                }
            }
        }
        __syncthreads();
    }

#pragma unroll
    for (int i = 0; i < 4; i++) {
        int s = i0 + i * 32 + ty;
        float* op = outp + ((size_t)b * SS + s) * HH + h * HD + tx * 4;
#pragma unroll
        for (int c = 0; c < 4; c++) {
            float2 p0 = unpk(acc[i][c * 2]), p1 = unpk(acc[i][c * 2 + 1]);
            float4 o4 = make_float4(p0.x, p0.y, p1.x, p1.y);
            *(float4*)(op + c * 16) = o4;
        }
    }
}

// ---------------------------------------------------------------------------
extern "C" void kernel_launch(void* const* d_in, const int* in_sizes, int n_in,
                              void* d_out, int out_size)
{
    const float* query = (const float*)d_in[0];
    const float* key   = (const float*)d_in[1];
    const float* value = (const float*)d_in[2];
    const unsigned char* mask = (const unsigned char*)d_in[3];
    const float* Wq = (const float*)d_in[4];
    const float* bq = (const float*)d_in[5];
    const float* Wk = (const float*)d_in[6];
    const float* bk = (const float*)d_in[7];
    const float* Wv = (const float*)d_in[8];
    const float* bv = (const float*)d_in[9];

    float* outp = (float*)d_out;                        // [B,S,H]
    float* wts  = outp + (size_t)BB * SS * HH;          // [B,h,S,S]

    float *gq, *gk, *gv, *gkt, *gwt;
    cudaGetSymbolAddress((void**)&gq, g_q);
    cudaGetSymbolAddress((void**)&gk, g_k);
    cudaGetSymbolAddress((void**)&gv, g_v);
    cudaGetSymbolAddress((void**)&gkt, g_kt);
    cudaGetSymbolAddress((void**)&gwt, g_wt);

    cudaFuncSetAttribute(proj_kernel, cudaFuncAttributeMaxDynamicSharedMemorySize,
                         PROJ_SMEM);
    cudaFuncSetAttribute(score_kernel, cudaFuncAttributeMaxDynamicSharedMemorySize,
                         SCORE_SMEM);
    cudaFuncSetAttribute(pv_kernel, cudaFuncAttributeMaxDynamicSharedMemorySize,
                         PV_SMEM);

    dim3 tb(32, 8);

    transpose_w3<<<dim3(32, 32, 3), tb>>>(Wq, Wk, Wv, gwt);

    dim3 pgrid(HH / 128, NROWS / 64, 3);
    proj_kernel<<<pgrid, 128, PROJ_SMEM>>>(query, key, value, gwt, bq, bk, bv, gq, gk, gv);

    dim3 tkgrid(SS / 32, HD / 32, BH);
    transpose_k<<<tkgrid, tb>>>(gk, gkt);

    dim3 sgrid(SS / 128 / 4, SS / 128, BH);
    score_kernel<<<sgrid, 256, SCORE_SMEM>>>(wts);

    softmax_kernel<<<(BH * SS) / 8, 256>>>(mask, wts);

    dim3 vgrid(SS / 128, BH);
    pv_kernel<<<vgrid, 128, PV_SMEM>>>(wts, outp);
}